// round 1
// baseline (speedup 1.0000x reference)
#include <cuda_runtime.h>

#define B_ 2
#define S_ 2048
#define H_ 4096
#define NH_ 32
#define HD_ 128
#define MTOK (B_ * S_)     /* 4096 tokens */
#define NQKV (3 * H_)      /* 12288 */
#define ELEMS (B_ * NH_ * S_ * HD_) /* 16777216 */

// ---------------- scratch (device globals: allocation-free) ----------------
__device__ float g_Q[ELEMS];
__device__ float g_K[ELEMS];
__device__ float g_V[ELEMS];
__device__ float g_ctx[(size_t)MTOK * H_];

// ---------------- fp32 tiled GEMM: C[m][o] = sum_k A[m][k] * W[o][k] -------
// mode 0: epilogue adds b_qkv and scatters into g_Q/g_K/g_V (de-interleave)
// mode 1: A := g_ctx, epilogue adds b_dense + residual, writes d_out
__global__ __launch_bounds__(256)
void sgemm_kernel(const float* __restrict__ A, const float* __restrict__ W,
                  const float* __restrict__ bias, const float* __restrict__ resid,
                  float* __restrict__ out, int N, int K, int mode)
{
    __shared__ float As[8][128];
    __shared__ float Bs[8][128];
    const int tid = threadIdx.x;
    const int mBase = blockIdx.y * 128;
    const int nBase = blockIdx.x * 128;
    const int tx = tid & 15, ty = tid >> 4;
    const int lRow = tid >> 1;          // 0..127
    const int lCol = (tid & 1) * 4;     // 0 or 4

    const float* Aeff = (mode == 1) ? (const float*)g_ctx : A;
    const float* Ap = Aeff + (size_t)(mBase + lRow) * K + lCol;
    const float* Bp = W    + (size_t)(nBase + lRow) * K + lCol;

    float acc[8][8];
#pragma unroll
    for (int i = 0; i < 8; i++)
#pragma unroll
        for (int j = 0; j < 8; j++) acc[i][j] = 0.f;

    float4 a4 = *(const float4*)Ap;
    float4 b4 = *(const float4*)Bp;

    for (int k0 = 0; k0 < K; k0 += 8) {
        As[lCol + 0][lRow] = a4.x; As[lCol + 1][lRow] = a4.y;
        As[lCol + 2][lRow] = a4.z; As[lCol + 3][lRow] = a4.w;
        Bs[lCol + 0][lRow] = b4.x; Bs[lCol + 1][lRow] = b4.y;
        Bs[lCol + 2][lRow] = b4.z; Bs[lCol + 3][lRow] = b4.w;
        __syncthreads();
        if (k0 + 8 < K) {   // prefetch next tile (overlap with compute)
            a4 = *(const float4*)(Ap + k0 + 8);
            b4 = *(const float4*)(Bp + k0 + 8);
        }
#pragma unroll
        for (int kk = 0; kk < 8; kk++) {
            float ra[8], rb[8];
            *(float4*)(ra)     = *(const float4*)&As[kk][ty * 8];
            *(float4*)(ra + 4) = *(const float4*)&As[kk][ty * 8 + 4];
            *(float4*)(rb)     = *(const float4*)&Bs[kk][tx * 8];
            *(float4*)(rb + 4) = *(const float4*)&Bs[kk][tx * 8 + 4];
#pragma unroll
            for (int i = 0; i < 8; i++)
#pragma unroll
                for (int j = 0; j < 8; j++)
                    acc[i][j] += ra[i] * rb[j];
        }
        __syncthreads();
    }

    if (mode == 0) {
        // scatter QKV: o = nh*384 + t*128 + d  ->  [b][nh][s][d]
#pragma unroll
        for (int i = 0; i < 8; i++) {
            int m = mBase + ty * 8 + i;
            int b = m >> 11;       // /2048
            int s = m & 2047;
#pragma unroll
            for (int j = 0; j < 8; j++) {
                int o = nBase + tx * 8 + j;
                float v = acc[i][j] + bias[o];
                int nh  = o / 384;
                int rem = o - nh * 384;
                int t   = rem >> 7;
                int d   = rem & 127;
                float* dst = (t == 0) ? g_Q : (t == 1) ? g_K : g_V;
                dst[(((size_t)b * NH_ + nh) * S_ + s) * HD_ + d] = v;
            }
        }
    } else {
#pragma unroll
        for (int i = 0; i < 8; i++) {
            int m = mBase + ty * 8 + i;
#pragma unroll
            for (int j0 = 0; j0 < 8; j0 += 4) {
                int o = nBase + tx * 8 + j0;
                float4 r4 = *(const float4*)&resid[(size_t)m * H_ + o];
                float4 bi = *(const float4*)&bias[o];
                float4 ov;
                ov.x = acc[i][j0 + 0] + bi.x + r4.x;
                ov.y = acc[i][j0 + 1] + bi.y + r4.y;
                ov.z = acc[i][j0 + 2] + bi.z + r4.z;
                ov.w = acc[i][j0 + 3] + bi.w + r4.w;
                *(float4*)&out[(size_t)m * H_ + o] = ov;
            }
        }
    }
}

// ---------------- flash attention (fp32, causal + alibi) -------------------
// grid: (S/64 q-tiles, B*NH).  64 q-rows per block, 64-key tiles, online softmax.
#define QLD 132          /* 128 + 4 pad, keeps float4 alignment */
#define SLD 68           /* 64 + 4 pad */

__global__ __launch_bounds__(256)
void attn_kernel(const float* __restrict__ alibi)
{
    extern __shared__ float sm[];
    float* Qs   = sm;                  // 64 * 132
    float* KVs  = Qs  + 64 * QLD;      // 64 * 132 (K then reused for V)
    float* Ss   = KVs + 64 * QLD;      // 64 * 68
    float* mrow = Ss  + 64 * SLD;      // 64
    float* lrow = mrow + 64;           // 64
    float* arow = lrow + 64;           // 64
    float* als  = arow + 64;           // 64

    const int tid = threadIdx.x;
    const int qt = gridDim.x - 1 - blockIdx.x;   // heavy tiles first
    const int bh = blockIdx.y;                   // b*NH + nh
    const int b  = bh >> 5;
    const int nh = bh & 31;

    const float* Qg  = g_Q + (size_t)bh * S_ * HD_ + (size_t)qt * 64 * HD_;
    const float* Kg  = g_K + (size_t)bh * S_ * HD_;
    const float* Vg  = g_V + (size_t)bh * S_ * HD_;
    const float* alg = alibi + (size_t)bh * S_;

    // load Q tile
    for (int x = tid * 4; x < 64 * 128; x += 1024) {
        int r = x >> 7, d = x & 127;
        *(float4*)&Qs[r * QLD + d] = *(const float4*)(Qg + (size_t)r * HD_ + d);
    }
    if (tid < 64) { mrow[tid] = -1e30f; lrow[tid] = 0.f; }

    const int tx = tid & 15, ty = tid >> 4;   // score stage: 4x4 tile each
    const int tx2 = tid & 31, ty2 = tid >> 5; // PV stage: 8 rows x 4 cols each
    float cacc[8][4];
#pragma unroll
    for (int i = 0; i < 8; i++)
#pragma unroll
        for (int j = 0; j < 4; j++) cacc[i][j] = 0.f;

    const float inv_norm = 0.08838834764831845f;  // 1/sqrt(128)
    const int nTiles = qt + 1;                    // causal: only k-tiles <= q-tile

    for (int jt = 0; jt < nTiles; jt++) {
        // load K tile + alibi slice
        for (int x = tid * 4; x < 64 * 128; x += 1024) {
            int r = x >> 7, d = x & 127;
            *(float4*)&KVs[r * QLD + d] =
                *(const float4*)(Kg + ((size_t)(jt * 64 + r)) * HD_ + d);
        }
        if (tid < 64) als[tid] = alg[jt * 64 + tid];
        __syncthreads();

        // scores: S = Q K^T
        float sacc[4][4];
#pragma unroll
        for (int i = 0; i < 4; i++)
#pragma unroll
            for (int j = 0; j < 4; j++) sacc[i][j] = 0.f;

        for (int d = 0; d < 128; d += 4) {
            float4 q4[4], k4[4];
#pragma unroll
            for (int i = 0; i < 4; i++) q4[i] = *(const float4*)&Qs[(ty * 4 + i) * QLD + d];
#pragma unroll
            for (int j = 0; j < 4; j++) k4[j] = *(const float4*)&KVs[(tx * 4 + j) * QLD + d];
#pragma unroll
            for (int i = 0; i < 4; i++)
#pragma unroll
                for (int j = 0; j < 4; j++) {
                    sacc[i][j] += q4[i].x * k4[j].x;
                    sacc[i][j] += q4[i].y * k4[j].y;
                    sacc[i][j] += q4[i].z * k4[j].z;
                    sacc[i][j] += q4[i].w * k4[j].w;
                }
        }
        // scale + alibi + causal mask, write to smem
#pragma unroll
        for (int i = 0; i < 4; i++) {
            int q = qt * 64 + ty * 4 + i;
            float4 ov;
            {
                int kg = jt * 64 + tx * 4;
                ov.x = (kg + 0 > q) ? -100000.0f : sacc[i][0] * inv_norm + als[tx * 4 + 0];
                ov.y = (kg + 1 > q) ? -100000.0f : sacc[i][1] * inv_norm + als[tx * 4 + 1];
                ov.z = (kg + 2 > q) ? -100000.0f : sacc[i][2] * inv_norm + als[tx * 4 + 2];
                ov.w = (kg + 3 > q) ? -100000.0f : sacc[i][3] * inv_norm + als[tx * 4 + 3];
            }
            *(float4*)&Ss[(ty * 4 + i) * SLD + tx * 4] = ov;
        }
        __syncthreads();

        // online softmax: 4 threads per row
        {
            int r = tid >> 2, sub = tid & 3;
            float mloc = -1e30f;
            for (int c = sub * 16; c < sub * 16 + 16; c++)
                mloc = fmaxf(mloc, Ss[r * SLD + c]);
            mloc = fmaxf(mloc, __shfl_xor_sync(0xffffffffu, mloc, 1));
            mloc = fmaxf(mloc, __shfl_xor_sync(0xffffffffu, mloc, 2));
            float mold = mrow[r];
            float mnew = fmaxf(mold, mloc);
            float sloc = 0.f;
            for (int c = sub * 16; c < sub * 16 + 16; c++) {
                float p = __expf(Ss[r * SLD + c] - mnew);
                Ss[r * SLD + c] = p;
                sloc += p;
            }
            sloc += __shfl_xor_sync(0xffffffffu, sloc, 1);
            sloc += __shfl_xor_sync(0xffffffffu, sloc, 2);
            if (sub == 0) {
                float al = __expf(mold - mnew);
                arow[r] = al;
                mrow[r] = mnew;
                lrow[r] = lrow[r] * al + sloc;
            }
        }

        // load V tile into the (now-free) KV buffer
        for (int x = tid * 4; x < 64 * 128; x += 1024) {
            int r = x >> 7, d = x & 127;
            *(float4*)&KVs[r * QLD + d] =
                *(const float4*)(Vg + ((size_t)(jt * 64 + r)) * HD_ + d);
        }
        __syncthreads();

        // rescale + accumulate ctx += P * V
#pragma unroll
        for (int i = 0; i < 8; i++) {
            float al = arow[ty2 * 8 + i];
#pragma unroll
            for (int j = 0; j < 4; j++) cacc[i][j] *= al;
        }
        for (int k = 0; k < 64; k++) {
            float4 v4 = *(const float4*)&KVs[k * QLD + tx2 * 4];
#pragma unroll
            for (int i = 0; i < 8; i++) {
                float p = Ss[(ty2 * 8 + i) * SLD + k];
                cacc[i][0] += p * v4.x;
                cacc[i][1] += p * v4.y;
                cacc[i][2] += p * v4.z;
                cacc[i][3] += p * v4.w;
            }
        }
        __syncthreads();
    }

    // normalize + write ctx [b][s][nh*128 + c]
#pragma unroll
    for (int i = 0; i < 8; i++) {
        int r = ty2 * 8 + i;
        float invl = 1.f / lrow[r];
        int q = qt * 64 + r;
        float4 ov;
        ov.x = cacc[i][0] * invl;
        ov.y = cacc[i][1] * invl;
        ov.z = cacc[i][2] * invl;
        ov.w = cacc[i][3] * invl;
        *(float4*)&g_ctx[((size_t)(b * S_ + q)) * H_ + nh * HD_ + tx2 * 4] = ov;
    }
}

#define ATTN_SMEM ((64 * QLD * 2 + 64 * SLD + 4 * 64) * 4)

extern "C" void kernel_launch(void* const* d_in, const int* in_sizes, int n_in,
                              void* d_out, int out_size)
{
    (void)in_sizes; (void)n_in; (void)out_size;
    const float* hidden   = (const float*)d_in[0];
    const float* residual = (const float*)d_in[1];
    const float* alibi    = (const float*)d_in[2];
    // d_in[3] = attention_mask: deterministic causal triu(k=1), applied analytically
    const float* W_qkv   = (const float*)d_in[4];
    const float* b_qkv   = (const float*)d_in[5];
    const float* W_dense = (const float*)d_in[6];
    const float* b_dense = (const float*)d_in[7];
    float* out = (float*)d_out;

    cudaFuncSetAttribute(attn_kernel, cudaFuncAttributeMaxDynamicSharedMemorySize, ATTN_SMEM);

    // 1) QKV projection + bias + de-interleave scatter
    sgemm_kernel<<<dim3(NQKV / 128, MTOK / 128), 256>>>(
        hidden, W_qkv, b_qkv, nullptr, nullptr, NQKV, H_, 0);

    // 2) causal attention with alibi (flash-style, online softmax)
    attn_kernel<<<dim3(S_ / 64, B_ * NH_), 256, ATTN_SMEM>>>(alibi);

    // 3) dense projection + bias + residual
    sgemm_kernel<<<dim3(H_ / 128, MTOK / 128), 256>>>(
        nullptr, W_dense, b_dense, residual, out, H_, H_, 1);
}

// round 5
// speedup vs baseline: 2.3647x; 2.3647x over previous
#include <cuda_runtime.h>
#include <cstdint>

#define B_ 2
#define S_ 2048
#define H_ 4096
#define NH_ 32
#define HD_ 128
#define MTOK (B_ * S_)
#define NQKV (3 * H_)
#define ELEMS (B_ * NH_ * S_ * HD_)

// ---------------- scratch (device globals: allocation-free) ----------------
__device__ float g_Q[ELEMS];
__device__ float g_K[ELEMS];
__device__ float g_V[ELEMS];
__device__ float g_ctx[(size_t)MTOK * H_];
__device__ float g_Ar[(size_t)MTOK * H_];        // hidden rounded to tf32
__device__ float g_Wq[(size_t)NQKV * H_];        // W_qkv rounded to tf32
__device__ float g_Wd[(size_t)H_ * H_];          // W_dense rounded to tf32

__device__ __forceinline__ uint32_t smem_u32(const void* p) {
    uint32_t a;
    asm("{ .reg .u64 t; cvta.to.shared.u64 t, %1; cvt.u32.u64 %0, t; }" : "=r"(a) : "l"(p));
    return a;
}

// ---------------- tf32 round-to-nearest conversion ----------------
// which: 0 -> g_Ar, 1 -> g_Wq, 2 -> g_Wd  (avoids cudaGetSymbolAddress)
__global__ __launch_bounds__(256)
void cvt_tf32_kernel(const float* __restrict__ src, int which, int n4)
{
    float* dst = (which == 0) ? g_Ar : (which == 1) ? g_Wq : g_Wd;
    int i = blockIdx.x * 256 + threadIdx.x;
    if (i >= n4) return;
    float4 v = ((const float4*)src)[i];
    uint32_t a, b, c, d;
    asm("cvt.rna.tf32.f32 %0, %1;" : "=r"(a) : "f"(v.x));
    asm("cvt.rna.tf32.f32 %0, %1;" : "=r"(b) : "f"(v.y));
    asm("cvt.rna.tf32.f32 %0, %1;" : "=r"(c) : "f"(v.z));
    asm("cvt.rna.tf32.f32 %0, %1;" : "=r"(d) : "f"(v.w));
    float4 o;
    o.x = __uint_as_float(a); o.y = __uint_as_float(b);
    o.z = __uint_as_float(c); o.w = __uint_as_float(d);
    ((float4*)dst)[i] = o;
}

// ============== mma.sync tf32 GEMM: C[m][o] = sum_k A[m][k]*W[o][k] ========
// CTA tile M=128 x N=256, 8 warps (2x4), warp tile 64x64, K-chunk 32,
// 3-stage cp.async pipeline, XOR-swizzled smem (conflict-free lds.32).
#define KCH 32
#define ASZB (128 * KCH * 4)      /* 16384 B */
#define BSZB (256 * KCH * 4)      /* 32768 B */
#define STG  (ASZB + BSZB)        /* 49152 B */
#define NSTG 3
#define GSMEM (NSTG * STG)        /* 147456 B */

__device__ __forceinline__ uint32_t lds_sw(const char* base, int row, int col) {
    uint32_t off = (uint32_t)(row * 128 + col * 4);
    off ^= (uint32_t)((row & 7) << 4);
    return *(const uint32_t*)(base + off);
}
__device__ __forceinline__ void mma_tf32(float* c, const uint32_t* a, const uint32_t* b) {
    asm volatile("mma.sync.aligned.m16n8k8.row.col.f32.tf32.tf32.f32 "
        "{%0,%1,%2,%3}, {%4,%5,%6,%7}, {%8,%9}, {%0,%1,%2,%3};"
        : "+f"(c[0]), "+f"(c[1]), "+f"(c[2]), "+f"(c[3])
        : "r"(a[0]), "r"(a[1]), "r"(a[2]), "r"(a[3]), "r"(b[0]), "r"(b[1]));
}

__global__ __launch_bounds__(256, 1)
void gemm_mma_kernel(const float* __restrict__ bias, const float* __restrict__ resid,
                     float* __restrict__ out, int mode)
{
    extern __shared__ char smraw[];
    const uint32_t sbase = smem_u32(smraw);

    const int tid = threadIdx.x;
    const int wid = tid >> 5;
    const int lane = tid & 31;
    const int g = lane >> 2, t = lane & 3;
    const int warpM = wid >> 2;     // 0..1
    const int warpN = wid & 3;      // 0..3
    const int mBase = blockIdx.x * 128;
    const int nBase = blockIdx.y * 256;
    const int K = H_;
    const int nk = K / KCH;         // 128

    const float* Asrc = mode ? (const float*)g_ctx : (const float*)g_Ar;
    const float* Wsrc = mode ? (const float*)g_Wd  : (const float*)g_Wq;

    // loader mapping: 12 float4 per thread per chunk (A: 1024, B: 2048)
    const float* src[12];
    uint32_t dstoff[12];
#pragma unroll
    for (int u = 0; u < 12; u++) {
        int idx = tid + 256 * u;
        if (idx < 1024) {
            int r = idx >> 3, c4 = idx & 7;
            src[u] = Asrc + (size_t)(mBase + r) * K + c4 * 4;
            dstoff[u] = (uint32_t)(r * 128 + ((c4 ^ (r & 7)) << 4));
        } else {
            int x = idx - 1024;
            int r = x >> 3, c4 = x & 7;
            src[u] = Wsrc + (size_t)(nBase + r) * K + c4 * 4;
            dstoff[u] = (uint32_t)(ASZB + r * 128 + ((c4 ^ (r & 7)) << 4));
        }
    }

    float acc[4][8][4];
#pragma unroll
    for (int mt = 0; mt < 4; mt++)
#pragma unroll
        for (int nt = 0; nt < 8; nt++)
#pragma unroll
            for (int q = 0; q < 4; q++) acc[mt][nt][q] = 0.f;

#define ISSUE(i) do { \
    uint32_t sb_ = sbase + ((i) % NSTG) * STG; \
    _Pragma("unroll") \
    for (int u = 0; u < 12; u++) { \
        asm volatile("cp.async.cg.shared.global [%0], [%1], 16;" \
                     :: "r"(sb_ + dstoff[u]), "l"(src[u] + (size_t)(i) * KCH) : "memory"); \
    } \
    asm volatile("cp.async.commit_group;" ::: "memory"); \
} while (0)

    ISSUE(0);
    ISSUE(1);

    for (int i = 0; i < nk; i++) {
        if (i < nk - 1)
            asm volatile("cp.async.wait_group 1;" ::: "memory");
        else
            asm volatile("cp.async.wait_group 0;" ::: "memory");
        __syncthreads();
        if (i + 2 < nk) ISSUE(i + 2);

        const char* sA = smraw + (i % NSTG) * STG;
        const char* sB = sA + ASZB;
#pragma unroll
        for (int k8 = 0; k8 < 4; k8++) {
            const int k0 = k8 * 8;
            uint32_t Af[4][4], Bf[8][2];
#pragma unroll
            for (int mt = 0; mt < 4; mt++) {
                int r0 = warpM * 64 + mt * 16 + g;
                Af[mt][0] = lds_sw(sA, r0,     k0 + t);
                Af[mt][1] = lds_sw(sA, r0 + 8, k0 + t);
                Af[mt][2] = lds_sw(sA, r0,     k0 + t + 4);
                Af[mt][3] = lds_sw(sA, r0 + 8, k0 + t + 4);
            }
#pragma unroll
            for (int nt = 0; nt < 8; nt++) {
                int rn = warpN * 64 + nt * 8 + g;
                Bf[nt][0] = lds_sw(sB, rn, k0 + t);
                Bf[nt][1] = lds_sw(sB, rn, k0 + t + 4);
            }
#pragma unroll
            for (int mt = 0; mt < 4; mt++)
#pragma unroll
                for (int nt = 0; nt < 8; nt++)
                    mma_tf32(acc[mt][nt], Af[mt], Bf[nt]);
        }
    }

    // ------------------------- epilogue -------------------------
#pragma unroll
    for (int mt = 0; mt < 4; mt++) {
        int r0 = mBase + warpM * 64 + mt * 16 + g;
#pragma unroll
        for (int nt = 0; nt < 8; nt++) {
            int o = nBase + warpN * 64 + nt * 8 + t * 2;
            float2 bi = *(const float2*)&bias[o];
            if (mode == 0) {
                int nh  = o / 384;
                int rem = o - nh * 384;
                int tt  = rem >> 7;
                int d   = rem & 127;
                float* dstg = (tt == 0) ? g_Q : (tt == 1) ? g_K : g_V;
                {
                    int bb = r0 >> 11, s = r0 & 2047;
                    float2 ov = { acc[mt][nt][0] + bi.x, acc[mt][nt][1] + bi.y };
                    *(float2*)&dstg[(((size_t)bb * NH_ + nh) * S_ + s) * HD_ + d] = ov;
                }
                {
                    int r1 = r0 + 8;
                    int bb = r1 >> 11, s = r1 & 2047;
                    float2 ov = { acc[mt][nt][2] + bi.x, acc[mt][nt][3] + bi.y };
                    *(float2*)&dstg[(((size_t)bb * NH_ + nh) * S_ + s) * HD_ + d] = ov;
                }
            } else {
                {
                    float2 rs = *(const float2*)&resid[(size_t)r0 * H_ + o];
                    float2 ov = { acc[mt][nt][0] + bi.x + rs.x, acc[mt][nt][1] + bi.y + rs.y };
                    *(float2*)&out[(size_t)r0 * H_ + o] = ov;
                }
                {
                    int r1 = r0 + 8;
                    float2 rs = *(const float2*)&resid[(size_t)r1 * H_ + o];
                    float2 ov = { acc[mt][nt][2] + bi.x + rs.x, acc[mt][nt][3] + bi.y + rs.y };
                    *(float2*)&out[(size_t)r1 * H_ + o] = ov;
                }
            }
        }
    }
}

// ---------------- flash attention (fp32, causal + alibi) -------------------
#define QLD 132
#define SLD 68

__global__ __launch_bounds__(256)
void attn_kernel(const float* __restrict__ alibi)
{
    extern __shared__ float sm[];
    float* Qs   = sm;
    float* KVs  = Qs  + 64 * QLD;
    float* Ss   = KVs + 64 * QLD;
    float* mrow = Ss  + 64 * SLD;
    float* lrow = mrow + 64;
    float* arow = lrow + 64;
    float* als  = arow + 64;

    const int tid = threadIdx.x;
    const int qt = gridDim.x - 1 - blockIdx.x;
    const int bh = blockIdx.y;
    const int b  = bh >> 5;
    const int nh = bh & 31;

    const float* Qg  = g_Q + (size_t)bh * S_ * HD_ + (size_t)qt * 64 * HD_;
    const float* Kg  = g_K + (size_t)bh * S_ * HD_;
    const float* Vg  = g_V + (size_t)bh * S_ * HD_;
    const float* alg = alibi + (size_t)bh * S_;

    for (int x = tid * 4; x < 64 * 128; x += 1024) {
        int r = x >> 7, d = x & 127;
        *(float4*)&Qs[r * QLD + d] = *(const float4*)(Qg + (size_t)r * HD_ + d);
    }
    if (tid < 64) { mrow[tid] = -1e30f; lrow[tid] = 0.f; }

    const int tx = tid & 15, ty = tid >> 4;
    const int tx2 = tid & 31, ty2 = tid >> 5;
    float cacc[8][4];
#pragma unroll
    for (int i = 0; i < 8; i++)
#pragma unroll
        for (int j = 0; j < 4; j++) cacc[i][j] = 0.f;

    const float inv_norm = 0.08838834764831845f;
    const int nTiles = qt + 1;

    for (int jt = 0; jt < nTiles; jt++) {
        for (int x = tid * 4; x < 64 * 128; x += 1024) {
            int r = x >> 7, d = x & 127;
            *(float4*)&KVs[r * QLD + d] =
                *(const float4*)(Kg + ((size_t)(jt * 64 + r)) * HD_ + d);
        }
        if (tid < 64) als[tid] = alg[jt * 64 + tid];
        __syncthreads();

        float sacc[4][4];
#pragma unroll
        for (int i = 0; i < 4; i++)
#pragma unroll
            for (int j = 0; j < 4; j++) sacc[i][j] = 0.f;

        for (int d = 0; d < 128; d += 4) {
            float4 q4[4], k4[4];
#pragma unroll
            for (int i = 0; i < 4; i++) q4[i] = *(const float4*)&Qs[(ty * 4 + i) * QLD + d];
#pragma unroll
            for (int j = 0; j < 4; j++) k4[j] = *(const float4*)&KVs[(tx * 4 + j) * QLD + d];
#pragma unroll
            for (int i = 0; i < 4; i++)
#pragma unroll
                for (int j = 0; j < 4; j++) {
                    sacc[i][j] += q4[i].x * k4[j].x;
                    sacc[i][j] += q4[i].y * k4[j].y;
                    sacc[i][j] += q4[i].z * k4[j].z;
                    sacc[i][j] += q4[i].w * k4[j].w;
                }
        }
#pragma unroll
        for (int i = 0; i < 4; i++) {
            int q = qt * 64 + ty * 4 + i;
            float4 ov;
            {
                int kg = jt * 64 + tx * 4;
                ov.x = (kg + 0 > q) ? -100000.0f : sacc[i][0] * inv_norm + als[tx * 4 + 0];
                ov.y = (kg + 1 > q) ? -100000.0f : sacc[i][1] * inv_norm + als[tx * 4 + 1];
                ov.z = (kg + 2 > q) ? -100000.0f : sacc[i][2] * inv_norm + als[tx * 4 + 2];
                ov.w = (kg + 3 > q) ? -100000.0f : sacc[i][3] * inv_norm + als[tx * 4 + 3];
            }
            *(float4*)&Ss[(ty * 4 + i) * SLD + tx * 4] = ov;
        }
        __syncthreads();

        {
            int r = tid >> 2, sub = tid & 3;
            float mloc = -1e30f;
            for (int c = sub * 16; c < sub * 16 + 16; c++)
                mloc = fmaxf(mloc, Ss[r * SLD + c]);
            mloc = fmaxf(mloc, __shfl_xor_sync(0xffffffffu, mloc, 1));
            mloc = fmaxf(mloc, __shfl_xor_sync(0xffffffffu, mloc, 2));
            float mold = mrow[r];
            float mnew = fmaxf(mold, mloc);
            float sloc = 0.f;
            for (int c = sub * 16; c < sub * 16 + 16; c++) {
                float p = __expf(Ss[r * SLD + c] - mnew);
                Ss[r * SLD + c] = p;
                sloc += p;
            }
            sloc += __shfl_xor_sync(0xffffffffu, sloc, 1);
            sloc += __shfl_xor_sync(0xffffffffu, sloc, 2);
            if (sub == 0) {
                float al = __expf(mold - mnew);
                arow[r] = al;
                mrow[r] = mnew;
                lrow[r] = lrow[r] * al + sloc;
            }
        }

        for (int x = tid * 4; x < 64 * 128; x += 1024) {
            int r = x >> 7, d = x & 127;
            *(float4*)&KVs[r * QLD + d] =
                *(const float4*)(Vg + ((size_t)(jt * 64 + r)) * HD_ + d);
        }
        __syncthreads();

#pragma unroll
        for (int i = 0; i < 8; i++) {
            float al = arow[ty2 * 8 + i];
#pragma unroll
            for (int j = 0; j < 4; j++) cacc[i][j] *= al;
        }
        for (int k = 0; k < 64; k++) {
            float4 v4 = *(const float4*)&KVs[k * QLD + tx2 * 4];
#pragma unroll
            for (int i = 0; i < 8; i++) {
                float p = Ss[(ty2 * 8 + i) * SLD + k];
                cacc[i][0] += p * v4.x;
                cacc[i][1] += p * v4.y;
                cacc[i][2] += p * v4.z;
                cacc[i][3] += p * v4.w;
            }
        }
        __syncthreads();
    }

#pragma unroll
    for (int i = 0; i < 8; i++) {
        int r = ty2 * 8 + i;
        float invl = 1.f / lrow[r];
        int q = qt * 64 + r;
        float4 ov;
        ov.x = cacc[i][0] * invl;
        ov.y = cacc[i][1] * invl;
        ov.z = cacc[i][2] * invl;
        ov.w = cacc[i][3] * invl;
        // round ctx to tf32 (unbiased) for the tensor-core dense GEMM
        uint32_t t0, t1, t2, t3;
        asm("cvt.rna.tf32.f32 %0, %1;" : "=r"(t0) : "f"(ov.x));
        asm("cvt.rna.tf32.f32 %0, %1;" : "=r"(t1) : "f"(ov.y));
        asm("cvt.rna.tf32.f32 %0, %1;" : "=r"(t2) : "f"(ov.z));
        asm("cvt.rna.tf32.f32 %0, %1;" : "=r"(t3) : "f"(ov.w));
        ov.x = __uint_as_float(t0); ov.y = __uint_as_float(t1);
        ov.z = __uint_as_float(t2); ov.w = __uint_as_float(t3);
        *(float4*)&g_ctx[((size_t)(b * S_ + q)) * H_ + nh * HD_ + tx2 * 4] = ov;
    }
}

#define ATTN_SMEM ((64 * QLD * 2 + 64 * SLD + 4 * 64) * 4)

extern "C" void kernel_launch(void* const* d_in, const int* in_sizes, int n_in,
                              void* d_out, int out_size)
{
    (void)in_sizes; (void)n_in; (void)out_size;
    const float* hidden   = (const float*)d_in[0];
    const float* residual = (const float*)d_in[1];
    const float* alibi    = (const float*)d_in[2];
    // d_in[3] = attention_mask: deterministic causal triu(k=1), applied analytically
    const float* W_qkv   = (const float*)d_in[4];
    const float* b_qkv   = (const float*)d_in[5];
    const float* W_dense = (const float*)d_in[6];
    const float* b_dense = (const float*)d_in[7];
    float* out = (float*)d_out;

    cudaFuncSetAttribute(gemm_mma_kernel, cudaFuncAttributeMaxDynamicSharedMemorySize, GSMEM);
    cudaFuncSetAttribute(attn_kernel, cudaFuncAttributeMaxDynamicSharedMemorySize, ATTN_SMEM);

    // 0) round GEMM inputs to tf32 (RNA, unbiased)
    cvt_tf32_kernel<<<(MTOK * H_ / 4 + 255) / 256, 256>>>(hidden, 0, MTOK * H_ / 4);
    cvt_tf32_kernel<<<(NQKV * H_ / 4 + 255) / 256, 256>>>(W_qkv, 1, NQKV * H_ / 4);
    cvt_tf32_kernel<<<(H_ * H_ / 4 + 255) / 256, 256>>>(W_dense, 2, H_ * H_ / 4);

    // 1) QKV projection (mma.sync tf32) + bias + de-interleave scatter
    gemm_mma_kernel<<<dim3(MTOK / 128, NQKV / 256), 256, GSMEM>>>(b_qkv, nullptr, nullptr, 0);

    // 2) causal attention with alibi (flash-style, online softmax, fp32)
    attn_kernel<<<dim3(S_ / 64, B_ * NH_), 256, ATTN_SMEM>>>(alibi);

    // 3) dense projection (mma.sync tf32) + bias + residual
    gemm_mma_kernel<<<dim3(MTOK / 128, H_ / 256), 256, GSMEM>>>(b_dense, residual, out, 1);
}

// round 6
// speedup vs baseline: 4.1190x; 1.7419x over previous
#include <cuda_runtime.h>
#include <cstdint>

#define B_ 2
#define S_ 2048
#define H_ 4096
#define NH_ 32
#define HD_ 128
#define MTOK (B_ * S_)
#define NQKV (3 * H_)
#define ELEMS (B_ * NH_ * S_ * HD_)

// ---------------- scratch (device globals: allocation-free) ----------------
__device__ float g_Q[ELEMS];
__device__ float g_K[ELEMS];
__device__ float g_V[ELEMS];
__device__ float g_ctx[(size_t)MTOK * H_];
__device__ float g_Ar[(size_t)MTOK * H_];        // hidden rounded to tf32
__device__ float g_Wq[(size_t)NQKV * H_];        // W_qkv rounded to tf32
__device__ float g_Wd[(size_t)H_ * H_];          // W_dense rounded to tf32

__device__ __forceinline__ uint32_t smem_u32(const void* p) {
    uint32_t a;
    asm("{ .reg .u64 t; cvta.to.shared.u64 t, %1; cvt.u32.u64 %0, t; }" : "=r"(a) : "l"(p));
    return a;
}
__device__ __forceinline__ float rna_tf32(float x) {
    uint32_t u;
    asm("cvt.rna.tf32.f32 %0, %1;" : "=r"(u) : "f"(x));
    return __uint_as_float(u);
}

// ---------------- tf32 round-to-nearest conversion ----------------
__global__ __launch_bounds__(256)
void cvt_tf32_kernel(const float* __restrict__ src, int which, int n4)
{
    float* dst = (which == 0) ? g_Ar : (which == 1) ? g_Wq : g_Wd;
    int i = blockIdx.x * 256 + threadIdx.x;
    if (i >= n4) return;
    float4 v = ((const float4*)src)[i];
    float4 o;
    o.x = rna_tf32(v.x); o.y = rna_tf32(v.y);
    o.z = rna_tf32(v.z); o.w = rna_tf32(v.w);
    ((float4*)dst)[i] = o;
}

// ============== mma.sync tf32 GEMM: C[m][o] = sum_k A[m][k]*W[o][k] ========
#define KCH 32
#define ASZB (128 * KCH * 4)
#define BSZB (256 * KCH * 4)
#define STG  (ASZB + BSZB)
#define NSTG 3
#define GSMEM (NSTG * STG)

__device__ __forceinline__ uint32_t lds_sw(const char* base, int row, int col) {
    uint32_t off = (uint32_t)(row * 128 + col * 4);
    off ^= (uint32_t)((row & 7) << 4);
    return *(const uint32_t*)(base + off);
}
__device__ __forceinline__ void mma_tf32(float* c, const uint32_t* a, const uint32_t* b) {
    asm volatile("mma.sync.aligned.m16n8k8.row.col.f32.tf32.tf32.f32 "
        "{%0,%1,%2,%3}, {%4,%5,%6,%7}, {%8,%9}, {%0,%1,%2,%3};"
        : "+f"(c[0]), "+f"(c[1]), "+f"(c[2]), "+f"(c[3])
        : "r"(a[0]), "r"(a[1]), "r"(a[2]), "r"(a[3]), "r"(b[0]), "r"(b[1]));
}

__global__ __launch_bounds__(256, 1)
void gemm_mma_kernel(const float* __restrict__ bias, const float* __restrict__ resid,
                     float* __restrict__ out, int mode)
{
    extern __shared__ char smraw[];
    const uint32_t sbase = smem_u32(smraw);

    const int tid = threadIdx.x;
    const int wid = tid >> 5;
    const int lane = tid & 31;
    const int g = lane >> 2, t = lane & 3;
    const int warpM = wid >> 2;
    const int warpN = wid & 3;
    const int mBase = blockIdx.x * 128;
    const int nBase = blockIdx.y * 256;
    const int K = H_;
    const int nk = K / KCH;

    const float* Asrc = mode ? (const float*)g_ctx : (const float*)g_Ar;
    const float* Wsrc = mode ? (const float*)g_Wd  : (const float*)g_Wq;

    const float* src[12];
    uint32_t dstoff[12];
#pragma unroll
    for (int u = 0; u < 12; u++) {
        int idx = tid + 256 * u;
        if (idx < 1024) {
            int r = idx >> 3, c4 = idx & 7;
            src[u] = Asrc + (size_t)(mBase + r) * K + c4 * 4;
            dstoff[u] = (uint32_t)(r * 128 + ((c4 ^ (r & 7)) << 4));
        } else {
            int x = idx - 1024;
            int r = x >> 3, c4 = x & 7;
            src[u] = Wsrc + (size_t)(nBase + r) * K + c4 * 4;
            dstoff[u] = (uint32_t)(ASZB + r * 128 + ((c4 ^ (r & 7)) << 4));
        }
    }

    float acc[4][8][4];
#pragma unroll
    for (int mt = 0; mt < 4; mt++)
#pragma unroll
        for (int nt = 0; nt < 8; nt++)
#pragma unroll
            for (int q = 0; q < 4; q++) acc[mt][nt][q] = 0.f;

#define ISSUE(i) do { \
    uint32_t sb_ = sbase + ((i) % NSTG) * STG; \
    _Pragma("unroll") \
    for (int u = 0; u < 12; u++) { \
        asm volatile("cp.async.cg.shared.global [%0], [%1], 16;" \
                     :: "r"(sb_ + dstoff[u]), "l"(src[u] + (size_t)(i) * KCH) : "memory"); \
    } \
    asm volatile("cp.async.commit_group;" ::: "memory"); \
} while (0)

    ISSUE(0);
    ISSUE(1);

    for (int i = 0; i < nk; i++) {
        if (i < nk - 1)
            asm volatile("cp.async.wait_group 1;" ::: "memory");
        else
            asm volatile("cp.async.wait_group 0;" ::: "memory");
        __syncthreads();
        if (i + 2 < nk) ISSUE(i + 2);

        const char* sA = smraw + (i % NSTG) * STG;
        const char* sB = sA + ASZB;
#pragma unroll
        for (int k8 = 0; k8 < 4; k8++) {
            const int k0 = k8 * 8;
            uint32_t Af[4][4], Bf[8][2];
#pragma unroll
            for (int mt = 0; mt < 4; mt++) {
                int r0 = warpM * 64 + mt * 16 + g;
                Af[mt][0] = lds_sw(sA, r0,     k0 + t);
                Af[mt][1] = lds_sw(sA, r0 + 8, k0 + t);
                Af[mt][2] = lds_sw(sA, r0,     k0 + t + 4);
                Af[mt][3] = lds_sw(sA, r0 + 8, k0 + t + 4);
            }
#pragma unroll
            for (int nt = 0; nt < 8; nt++) {
                int rn = warpN * 64 + nt * 8 + g;
                Bf[nt][0] = lds_sw(sB, rn, k0 + t);
                Bf[nt][1] = lds_sw(sB, rn, k0 + t + 4);
            }
#pragma unroll
            for (int mt = 0; mt < 4; mt++)
#pragma unroll
                for (int nt = 0; nt < 8; nt++)
                    mma_tf32(acc[mt][nt], Af[mt], Bf[nt]);
        }
    }

#pragma unroll
    for (int mt = 0; mt < 4; mt++) {
        int r0 = mBase + warpM * 64 + mt * 16 + g;
#pragma unroll
        for (int nt = 0; nt < 8; nt++) {
            int o = nBase + warpN * 64 + nt * 8 + t * 2;
            float2 bi = *(const float2*)&bias[o];
            if (mode == 0) {
                int nh  = o / 384;
                int rem = o - nh * 384;
                int tt  = rem >> 7;
                int d   = rem & 127;
                float* dstg = (tt == 0) ? g_Q : (tt == 1) ? g_K : g_V;
                {
                    int bb = r0 >> 11, s = r0 & 2047;
                    // pre-round to tf32 (RNA): attention mma consumes these
                    float2 ov = { rna_tf32(acc[mt][nt][0] + bi.x),
                                  rna_tf32(acc[mt][nt][1] + bi.y) };
                    *(float2*)&dstg[(((size_t)bb * NH_ + nh) * S_ + s) * HD_ + d] = ov;
                }
                {
                    int r1 = r0 + 8;
                    int bb = r1 >> 11, s = r1 & 2047;
                    float2 ov = { rna_tf32(acc[mt][nt][2] + bi.x),
                                  rna_tf32(acc[mt][nt][3] + bi.y) };
                    *(float2*)&dstg[(((size_t)bb * NH_ + nh) * S_ + s) * HD_ + d] = ov;
                }
            } else {
                {
                    float2 rs = *(const float2*)&resid[(size_t)r0 * H_ + o];
                    float2 ov = { acc[mt][nt][0] + bi.x + rs.x, acc[mt][nt][1] + bi.y + rs.y };
                    *(float2*)&out[(size_t)r0 * H_ + o] = ov;
                }
                {
                    int r1 = r0 + 8;
                    float2 rs = *(const float2*)&resid[(size_t)r1 * H_ + o];
                    float2 ov = { acc[mt][nt][2] + bi.x + rs.x, acc[mt][nt][3] + bi.y + rs.y };
                    *(float2*)&out[(size_t)r1 * H_ + o] = ov;
                }
            }
        }
    }
}

// ============ flash attention on tf32 mma (causal + alibi) =================
// CTA: 128 q-rows, 8 warps x 16 rows. K-tiles of 64, double-buffered K,
// pipelined V. Softmax in registers, P staged through swizzled smem.
__device__ __forceinline__ float ld128sw(const float* base, int r, int c) {
    return base[(r * 32 + (((c >> 2) ^ (r & 7)))) * 4 + (c & 3)];
}
__device__ __forceinline__ float ldPsw(const float* base, int r, int c) {
    return base[(r * 16 + (((c >> 2) ^ (r & 7)))) * 4 + (c & 3)];
}
__device__ __forceinline__ void stPsw(float* base, int r, int c, float p0, float p1) {
    float* p = &base[(r * 16 + (((c >> 2) ^ (r & 7)))) * 4 + (c & 3)];
    p[0] = p0; p[1] = p1;
}

#define AT_SMEM ((128 * 128 + 3 * 64 * 128 + 128 * 64 + 2048) * 4)  /* 204800 */

__global__ __launch_bounds__(256, 1)
void attn_mma_kernel(const float* __restrict__ alibi)
{
    extern __shared__ float sm[];
    float* Qs  = sm;                       // 128 x 128
    float* Ks0 = Qs  + 128 * 128;          // 64 x 128
    float* Ks1 = Ks0 + 64 * 128;           // 64 x 128
    float* Vs  = Ks1 + 64 * 128;           // 64 x 128
    float* Ps  = Vs  + 64 * 128;           // 128 x 64
    float* als = Ps  + 128 * 64;           // 2048

    const int tid = threadIdx.x;
    const int wid = tid >> 5;
    const int lane = tid & 31;
    const int g = lane >> 2, t = lane & 3;
    const int bh = blockIdx.x;             // head-major: heavy tiles spread
    const int qt = (int)gridDim.y - 1 - (int)blockIdx.y;
    const int b = bh >> 5, nh = bh & 31;
    const int qBase = qt * 128;

    const float* Qg  = g_Q + (size_t)bh * S_ * HD_ + (size_t)qBase * HD_;
    const float* Kg  = g_K + (size_t)bh * S_ * HD_;
    const float* Vg  = g_V + (size_t)bh * S_ * HD_;
    const float* alg = alibi + (size_t)bh * S_;

    const uint32_t sQ  = smem_u32(Qs);
    const uint32_t sK0 = smem_u32(Ks0);
    const uint32_t sK1 = smem_u32(Ks1);
    const uint32_t sV  = smem_u32(Vs);
    const uint32_t sAl = smem_u32(als);

    // group 0: Q tile + whole alibi row
#pragma unroll
    for (int u = 0; u < 16; u++) {
        int idx = tid + 256 * u;
        int r = idx >> 5, c4 = idx & 31;
        uint32_t doff = (uint32_t)((r * 32 + (c4 ^ (r & 7))) * 16);
        asm volatile("cp.async.cg.shared.global [%0], [%1], 16;"
            :: "r"(sQ + doff), "l"(Qg + (size_t)r * 128 + c4 * 4) : "memory");
    }
#pragma unroll
    for (int u = 0; u < 2; u++) {
        int idx = tid + 256 * u;
        asm volatile("cp.async.cg.shared.global [%0], [%1], 16;"
            :: "r"(sAl + idx * 16), "l"(alg + idx * 4) : "memory");
    }
    asm volatile("cp.async.commit_group;" ::: "memory");

#define KV_ISSUE(sbuf, srcp, kb) do { \
    _Pragma("unroll") \
    for (int u = 0; u < 8; u++) { \
        int idx = tid + 256 * u; \
        int r = idx >> 5, c4 = idx & 31; \
        uint32_t doff = (uint32_t)((r * 32 + (c4 ^ (r & 7))) * 16); \
        asm volatile("cp.async.cg.shared.global [%0], [%1], 16;" \
            :: "r"((sbuf) + doff), "l"((srcp) + (size_t)((kb) + r) * 128 + c4 * 4) : "memory"); \
    } \
    asm volatile("cp.async.commit_group;" ::: "memory"); \
} while (0)

    KV_ISSUE(sK0, Kg, 0);                    // K[0]

    float o[16][4];
#pragma unroll
    for (int nt = 0; nt < 16; nt++)
#pragma unroll
        for (int q = 0; q < 4; q++) o[nt][q] = 0.f;
    float m0 = -1e30f, m1 = -1e30f, l0 = 0.f, l1 = 0.f;

    const float inv_norm = 0.08838834764831845f;
    const int nT = 2 * qt + 2;
    const int rowg0 = qBase + wid * 16 + g;
    const int rowg1 = rowg0 + 8;

    for (int jt = 0; jt < nT; jt++) {
        const int kB = jt * 64;
        KV_ISSUE(sV, Vg, kB);
        asm volatile("cp.async.wait_group 1;" ::: "memory");   // K[jt] (+Q on jt=0)
        __syncthreads();

        const float* Kc = (jt & 1) ? Ks1 : Ks0;

        // ---------------- scores: S = Q K^T (16x64 per warp) ----------------
        float s[8][4];
#pragma unroll
        for (int nt = 0; nt < 8; nt++)
#pragma unroll
            for (int q = 0; q < 4; q++) s[nt][q] = 0.f;

#pragma unroll
        for (int k8 = 0; k8 < 16; k8++) {
            const int k0 = k8 * 8;
            uint32_t a[4];
            a[0] = __float_as_uint(ld128sw(Qs, wid * 16 + g,     k0 + t));
            a[1] = __float_as_uint(ld128sw(Qs, wid * 16 + g + 8, k0 + t));
            a[2] = __float_as_uint(ld128sw(Qs, wid * 16 + g,     k0 + t + 4));
            a[3] = __float_as_uint(ld128sw(Qs, wid * 16 + g + 8, k0 + t + 4));
#pragma unroll
            for (int nt = 0; nt < 8; nt++) {
                uint32_t bfr[2];
                bfr[0] = __float_as_uint(ld128sw(Kc, nt * 8 + g, k0 + t));
                bfr[1] = __float_as_uint(ld128sw(Kc, nt * 8 + g, k0 + t + 4));
                mma_tf32(s[nt], a, bfr);
            }
        }

        // prefetch K[jt+1] while V[jt] finishes
        if (jt + 1 < nT) {
            KV_ISSUE((jt & 1) ? sK0 : sK1, Kg, kB + 64);
            asm volatile("cp.async.wait_group 1;" ::: "memory");   // V[jt]
        } else {
            asm volatile("cp.async.wait_group 0;" ::: "memory");
        }
        __syncthreads();

        // ---------------- scale + alibi + causal mask ----------------
        const bool domask = (jt >= 2 * qt);
        float ml0 = -1e30f, ml1 = -1e30f;
#pragma unroll
        for (int nt = 0; nt < 8; nt++) {
            int c0 = kB + nt * 8 + 2 * t;
            float a0 = als[c0], a1 = als[c0 + 1];
            s[nt][0] = s[nt][0] * inv_norm + a0;
            s[nt][1] = s[nt][1] * inv_norm + a1;
            s[nt][2] = s[nt][2] * inv_norm + a0;
            s[nt][3] = s[nt][3] * inv_norm + a1;
            if (domask) {
                if (c0 > rowg0)     s[nt][0] = -1e30f;
                if (c0 + 1 > rowg0) s[nt][1] = -1e30f;
                if (c0 > rowg1)     s[nt][2] = -1e30f;
                if (c0 + 1 > rowg1) s[nt][3] = -1e30f;
            }
            ml0 = fmaxf(ml0, fmaxf(s[nt][0], s[nt][1]));
            ml1 = fmaxf(ml1, fmaxf(s[nt][2], s[nt][3]));
        }
        ml0 = fmaxf(ml0, __shfl_xor_sync(0xffffffffu, ml0, 1));
        ml0 = fmaxf(ml0, __shfl_xor_sync(0xffffffffu, ml0, 2));
        ml1 = fmaxf(ml1, __shfl_xor_sync(0xffffffffu, ml1, 1));
        ml1 = fmaxf(ml1, __shfl_xor_sync(0xffffffffu, ml1, 2));

        float mn0 = fmaxf(m0, ml0), mn1 = fmaxf(m1, ml1);
        float alpha0 = __expf(m0 - mn0), alpha1 = __expf(m1 - mn1);
        m0 = mn0; m1 = mn1;

        float ls0 = 0.f, ls1 = 0.f;
#pragma unroll
        for (int nt = 0; nt < 8; nt++) {
            float p0 = __expf(s[nt][0] - mn0);
            float p1 = __expf(s[nt][1] - mn0);
            float p2 = __expf(s[nt][2] - mn1);
            float p3 = __expf(s[nt][3] - mn1);
            ls0 += p0 + p1;
            ls1 += p2 + p3;
            int c = nt * 8 + 2 * t;
            stPsw(Ps, wid * 16 + g,     c, rna_tf32(p0), rna_tf32(p1));
            stPsw(Ps, wid * 16 + g + 8, c, rna_tf32(p2), rna_tf32(p3));
        }
        ls0 += __shfl_xor_sync(0xffffffffu, ls0, 1);
        ls0 += __shfl_xor_sync(0xffffffffu, ls0, 2);
        ls1 += __shfl_xor_sync(0xffffffffu, ls1, 1);
        ls1 += __shfl_xor_sync(0xffffffffu, ls1, 2);
        l0 = l0 * alpha0 + ls0;
        l1 = l1 * alpha1 + ls1;

#pragma unroll
        for (int nt = 0; nt < 16; nt++) {
            o[nt][0] *= alpha0; o[nt][1] *= alpha0;
            o[nt][2] *= alpha1; o[nt][3] *= alpha1;
        }
        __syncwarp();   // P is warp-local: rows w*16.. written & read by this warp

        // ---------------- O += P V  (16x128 per warp, k=64) ----------------
#pragma unroll
        for (int k8 = 0; k8 < 8; k8++) {
            const int k0 = k8 * 8;
            uint32_t a[4];
            a[0] = __float_as_uint(ldPsw(Ps, wid * 16 + g,     k0 + t));
            a[1] = __float_as_uint(ldPsw(Ps, wid * 16 + g + 8, k0 + t));
            a[2] = __float_as_uint(ldPsw(Ps, wid * 16 + g,     k0 + t + 4));
            a[3] = __float_as_uint(ldPsw(Ps, wid * 16 + g + 8, k0 + t + 4));
#pragma unroll
            for (int nt = 0; nt < 16; nt++) {
                uint32_t bfr[2];
                bfr[0] = __float_as_uint(ld128sw(Vs, k0 + t,     nt * 8 + g));
                bfr[1] = __float_as_uint(ld128sw(Vs, k0 + t + 4, nt * 8 + g));
                mma_tf32(o[nt], a, bfr);
            }
        }
        __syncthreads();   // Vs reused next iteration
    }

    // ---------------- normalize + write ctx (tf32-rounded) ----------------
    const float inv0 = 1.f / l0, inv1 = 1.f / l1;
#pragma unroll
    for (int nt = 0; nt < 16; nt++) {
        int d = nh * HD_ + nt * 8 + 2 * t;
        float2 ov0 = { rna_tf32(o[nt][0] * inv0), rna_tf32(o[nt][1] * inv0) };
        float2 ov1 = { rna_tf32(o[nt][2] * inv1), rna_tf32(o[nt][3] * inv1) };
        *(float2*)&g_ctx[((size_t)(b * S_ + rowg0)) * H_ + d] = ov0;
        *(float2*)&g_ctx[((size_t)(b * S_ + rowg1)) * H_ + d] = ov1;
    }
}

extern "C" void kernel_launch(void* const* d_in, const int* in_sizes, int n_in,
                              void* d_out, int out_size)
{
    (void)in_sizes; (void)n_in; (void)out_size;
    const float* hidden   = (const float*)d_in[0];
    const float* residual = (const float*)d_in[1];
    const float* alibi    = (const float*)d_in[2];
    // d_in[3] = attention_mask: deterministic causal triu(k=1), applied analytically
    const float* W_qkv   = (const float*)d_in[4];
    const float* b_qkv   = (const float*)d_in[5];
    const float* W_dense = (const float*)d_in[6];
    const float* b_dense = (const float*)d_in[7];
    float* out = (float*)d_out;

    cudaFuncSetAttribute(gemm_mma_kernel, cudaFuncAttributeMaxDynamicSharedMemorySize, GSMEM);
    cudaFuncSetAttribute(attn_mma_kernel, cudaFuncAttributeMaxDynamicSharedMemorySize, AT_SMEM);

    // 0) round GEMM inputs to tf32 (RNA, unbiased)
    cvt_tf32_kernel<<<(MTOK * H_ / 4 + 255) / 256, 256>>>(hidden, 0, MTOK * H_ / 4);
    cvt_tf32_kernel<<<(NQKV * H_ / 4 + 255) / 256, 256>>>(W_qkv, 1, NQKV * H_ / 4);
    cvt_tf32_kernel<<<(H_ * H_ / 4 + 255) / 256, 256>>>(W_dense, 2, H_ * H_ / 4);

    // 1) QKV projection (mma tf32) + bias + de-interleave scatter (tf32-rounded)
    gemm_mma_kernel<<<dim3(MTOK / 128, NQKV / 256), 256, GSMEM>>>(b_qkv, nullptr, nullptr, 0);

    // 2) causal attention with alibi — tf32 mma flash kernel
    attn_mma_kernel<<<dim3(B_ * NH_, S_ / 128), 256, AT_SMEM>>>(alibi);

    // 3) dense projection (mma tf32) + bias + residual
    gemm_mma_kernel<<<dim3(MTOK / 128, H_ / 256), 256, GSMEM>>>(b_dense, residual, out, 1);
}

// round 8
// speedup vs baseline: 4.5929x; 1.1150x over previous
#include <cuda_runtime.h>
#include <cstdint>

#define B_ 2
#define S_ 2048
#define H_ 4096
#define NH_ 32
#define HD_ 128
#define MTOK (B_ * S_)
#define NQKV (3 * H_)
#define ELEMS (B_ * NH_ * S_ * HD_)

// ---------------- scratch (device globals: allocation-free) ----------------
__device__ float g_Q[ELEMS];
__device__ float g_K[ELEMS];
__device__ float g_V[ELEMS];
__device__ float g_ctx[(size_t)MTOK * H_];
__device__ float g_Ar[(size_t)MTOK * H_];
__device__ float g_Wq[(size_t)NQKV * H_];
__device__ float g_Wd[(size_t)H_ * H_];

__device__ __forceinline__ uint32_t smem_u32(const void* p) {
    uint32_t a;
    asm("{ .reg .u64 t; cvta.to.shared.u64 t, %1; cvt.u32.u64 %0, t; }" : "=r"(a) : "l"(p));
    return a;
}
__device__ __forceinline__ float rna_tf32(float x) {
    uint32_t u;
    asm("cvt.rna.tf32.f32 %0, %1;" : "=r"(u) : "f"(x));
    return __uint_as_float(u);
}
__device__ __forceinline__ void ldsm4(uint32_t* r, uint32_t addr) {
    asm volatile("ldmatrix.sync.aligned.m8n8.x4.shared.b16 {%0,%1,%2,%3}, [%4];"
        : "=r"(r[0]), "=r"(r[1]), "=r"(r[2]), "=r"(r[3]) : "r"(addr));
}
__device__ __forceinline__ void mma_tf32(float* c, const uint32_t* a, const uint32_t* b) {
    asm volatile("mma.sync.aligned.m16n8k8.row.col.f32.tf32.tf32.f32 "
        "{%0,%1,%2,%3}, {%4,%5,%6,%7}, {%8,%9}, {%0,%1,%2,%3};"
        : "+f"(c[0]), "+f"(c[1]), "+f"(c[2]), "+f"(c[3])
        : "r"(a[0]), "r"(a[1]), "r"(a[2]), "r"(a[3]), "r"(b[0]), "r"(b[1]));
}

// ---------------- tf32 round-to-nearest conversion ----------------
__global__ __launch_bounds__(256)
void cvt_tf32_kernel(const float* __restrict__ src, int which, int n4)
{
    float* dst = (which == 0) ? g_Ar : (which == 1) ? g_Wq : g_Wd;
    int i = blockIdx.x * 256 + threadIdx.x;
    if (i >= n4) return;
    float4 v = ((const float4*)src)[i];
    float4 o;
    o.x = rna_tf32(v.x); o.y = rna_tf32(v.y);
    o.z = rna_tf32(v.z); o.w = rna_tf32(v.w);
    ((float4*)dst)[i] = o;
}

// ============== mma.sync tf32 GEMM (ldmatrix fragments) ====================
#define KCH 32
#define ASZB (128 * KCH * 4)
#define BSZB (256 * KCH * 4)
#define STG  (ASZB + BSZB)
#define NSTG 3
#define GSMEM (NSTG * STG)

__global__ __launch_bounds__(256, 1)
void gemm_mma_kernel(const float* __restrict__ bias, const float* __restrict__ resid,
                     float* __restrict__ out, int mode)
{
    extern __shared__ char smraw[];
    const uint32_t sbase = smem_u32(smraw);

    const int tid = threadIdx.x;
    const int wid = tid >> 5;
    const int lane = tid & 31;
    const int g = lane >> 2, t = lane & 3;
    const int lr = lane & 7;            // row within 8x8 matrix
    const int lm = lane >> 3;           // matrix id 0..3
    const int warpM = wid >> 2;
    const int warpN = wid & 3;
    const int mBase = blockIdx.x * 128;
    const int nBase = blockIdx.y * 256;
    const int K = H_;
    const int nk = K / KCH;

    const float* Asrc = mode ? (const float*)g_ctx : (const float*)g_Ar;
    const float* Wsrc = mode ? (const float*)g_Wd  : (const float*)g_Wq;

    // ldmatrix per-lane row precompute
    uint32_t aOff[4]; uint32_t aR7[4];
#pragma unroll
    for (int mt = 0; mt < 4; mt++) {
        int row = warpM * 64 + mt * 16 + lr + ((lm & 1) << 3);
        aOff[mt] = (uint32_t)(row * 128); aR7[mt] = (uint32_t)(row & 7);
    }
    uint32_t bOff[4]; uint32_t bR7[4];
#pragma unroll
    for (int np = 0; np < 4; np++) {
        int row = warpN * 64 + np * 16 + lr + ((lm >> 1) << 3);
        bOff[np] = (uint32_t)(ASZB + row * 128); bR7[np] = (uint32_t)(row & 7);
    }
    const uint32_t aC = (uint32_t)(lm >> 1);
    const uint32_t bC = (uint32_t)(lm & 1);

    const float* src[12];
    uint32_t dstoff[12];
#pragma unroll
    for (int u = 0; u < 12; u++) {
        int idx = tid + 256 * u;
        if (idx < 1024) {
            int r = idx >> 3, c4 = idx & 7;
            src[u] = Asrc + (size_t)(mBase + r) * K + c4 * 4;
            dstoff[u] = (uint32_t)(r * 128 + ((c4 ^ (r & 7)) << 4));
        } else {
            int x = idx - 1024;
            int r = x >> 3, c4 = x & 7;
            src[u] = Wsrc + (size_t)(nBase + r) * K + c4 * 4;
            dstoff[u] = (uint32_t)(ASZB + r * 128 + ((c4 ^ (r & 7)) << 4));
        }
    }

    float acc[4][8][4];
#pragma unroll
    for (int mt = 0; mt < 4; mt++)
#pragma unroll
        for (int nt = 0; nt < 8; nt++)
#pragma unroll
            for (int q = 0; q < 4; q++) acc[mt][nt][q] = 0.f;

#define ISSUE(i) do { \
    uint32_t sb_ = sbase + ((i) % NSTG) * STG; \
    _Pragma("unroll") \
    for (int u = 0; u < 12; u++) { \
        asm volatile("cp.async.cg.shared.global [%0], [%1], 16;" \
                     :: "r"(sb_ + dstoff[u]), "l"(src[u] + (size_t)(i) * KCH) : "memory"); \
    } \
    asm volatile("cp.async.commit_group;" ::: "memory"); \
} while (0)

    ISSUE(0);
    ISSUE(1);

    for (int i = 0; i < nk; i++) {
        if (i < nk - 1)
            asm volatile("cp.async.wait_group 1;" ::: "memory");
        else
            asm volatile("cp.async.wait_group 0;" ::: "memory");
        __syncthreads();
        if (i + 2 < nk) ISSUE(i + 2);

        const uint32_t sst = sbase + (i % NSTG) * STG;
#pragma unroll
        for (int k8 = 0; k8 < 4; k8++) {
            const uint32_t ac4 = 2 * k8 + aC;
            const uint32_t bc4 = 2 * k8 + bC;
            uint32_t Af[4][4], Bf[4][4];
#pragma unroll
            for (int mt = 0; mt < 4; mt++)
                ldsm4(Af[mt], sst + aOff[mt] + ((ac4 ^ aR7[mt]) << 4));
#pragma unroll
            for (int np = 0; np < 4; np++)
                ldsm4(Bf[np], sst + bOff[np] + ((bc4 ^ bR7[np]) << 4));
#pragma unroll
            for (int mt = 0; mt < 4; mt++)
#pragma unroll
                for (int np = 0; np < 4; np++) {
                    mma_tf32(acc[mt][2 * np],     Af[mt], &Bf[np][0]);
                    mma_tf32(acc[mt][2 * np + 1], Af[mt], &Bf[np][2]);
                }
        }
    }

    // ------------------------- epilogue -------------------------
#pragma unroll
    for (int mt = 0; mt < 4; mt++) {
        int r0 = mBase + warpM * 64 + mt * 16 + g;
#pragma unroll
        for (int nt = 0; nt < 8; nt++) {
            int o = nBase + warpN * 64 + nt * 8 + t * 2;
            float2 bi = *(const float2*)&bias[o];
            if (mode == 0) {
                int nh  = o / 384;
                int rem = o - nh * 384;
                int tt  = rem >> 7;
                int d   = rem & 127;
                float* dstg = (tt == 0) ? g_Q : (tt == 1) ? g_K : g_V;
                {
                    int bb = r0 >> 11, s = r0 & 2047;
                    float2 ov = { rna_tf32(acc[mt][nt][0] + bi.x),
                                  rna_tf32(acc[mt][nt][1] + bi.y) };
                    *(float2*)&dstg[(((size_t)bb * NH_ + nh) * S_ + s) * HD_ + d] = ov;
                }
                {
                    int r1 = r0 + 8;
                    int bb = r1 >> 11, s = r1 & 2047;
                    float2 ov = { rna_tf32(acc[mt][nt][2] + bi.x),
                                  rna_tf32(acc[mt][nt][3] + bi.y) };
                    *(float2*)&dstg[(((size_t)bb * NH_ + nh) * S_ + s) * HD_ + d] = ov;
                }
            } else {
                {
                    float2 rs = *(const float2*)&resid[(size_t)r0 * H_ + o];
                    float2 ov = { acc[mt][nt][0] + bi.x + rs.x, acc[mt][nt][1] + bi.y + rs.y };
                    *(float2*)&out[(size_t)r0 * H_ + o] = ov;
                }
                {
                    int r1 = r0 + 8;
                    float2 rs = *(const float2*)&resid[(size_t)r1 * H_ + o];
                    float2 ov = { acc[mt][nt][2] + bi.x + rs.x, acc[mt][nt][3] + bi.y + rs.y };
                    *(float2*)&out[(size_t)r1 * H_ + o] = ov;
                }
            }
        }
    }
}

// ============ flash attention on tf32 mma + ldmatrix =======================
#define AT_SMEM ((128 * 128 + 3 * 64 * 128 + 128 * 64 + 2048) * 4)  /* 204800 */

__global__ __launch_bounds__(256, 1)
void attn_mma_kernel(const float* __restrict__ alibi)
{
    extern __shared__ float sm[];
    float* Qs  = sm;                       // 128 x 128 (512B rows, swizzled)
    float* Ks0 = Qs  + 128 * 128;          // 64 x 128
    float* Ks1 = Ks0 + 64 * 128;           // 64 x 128
    float* Vs  = Ks1 + 64 * 128;           // 64 x 128 -> transposed in place to 128 x 64
    float* Ps  = Vs  + 64 * 128;           // 128 x 64 (256B rows, swizzled)
    float* als = Ps  + 128 * 64;           // 2048

    const int tid = threadIdx.x;
    const int wid = tid >> 5;
    const int lane = tid & 31;
    const int g = lane >> 2, t = lane & 3;
    const int lr = lane & 7;
    const int lm = lane >> 3;
    const int bh = blockIdx.x;
    const int qt = (int)gridDim.y - 1 - (int)blockIdx.y;
    const int b = bh >> 5, nh = bh & 31;
    const int qBase = qt * 128;

    const float* Qg  = g_Q + (size_t)bh * S_ * HD_ + (size_t)qBase * HD_;
    const float* Kg  = g_K + (size_t)bh * S_ * HD_;
    const float* Vg  = g_V + (size_t)bh * S_ * HD_;
    const float* alg = alibi + (size_t)bh * S_;

    const uint32_t sQ  = smem_u32(Qs);
    const uint32_t sK0 = smem_u32(Ks0);
    const uint32_t sK1 = smem_u32(Ks1);
    const uint32_t sV  = smem_u32(Vs);
    const uint32_t sP  = smem_u32(Ps);
    const uint32_t sAl = smem_u32(als);

    // ldmatrix per-lane row precompute
    const uint32_t aC = (uint32_t)(lm >> 1);   // A-frag col select
    const uint32_t bC = (uint32_t)(lm & 1);    // B-frag col select
    // Q/P A-frag rows (this warp's 16 rows)
    const int aRow = wid * 16 + lr + ((lm & 1) << 3);
    const uint32_t aR7 = (uint32_t)(aRow & 7);
    const uint32_t qAOff = (uint32_t)(aRow * 512);
    const uint32_t pAOff = (uint32_t)(aRow * 256);
    // K B-frag rows: 4 nt-pairs over 64 keys
    uint32_t kOff[4], kR7[4];
#pragma unroll
    for (int np = 0; np < 4; np++) {
        int row = np * 16 + lr + ((lm >> 1) << 3);
        kOff[np] = (uint32_t)(row * 512); kR7[np] = (uint32_t)(row & 7);
    }
    // V(t) B-frag rows: 8 nt-pairs over 128 d-cols (256B rows after transpose)
    uint32_t vOff[8], vR7[8];
#pragma unroll
    for (int np = 0; np < 8; np++) {
        int row = np * 16 + lr + ((lm >> 1) << 3);
        vOff[np] = (uint32_t)(row * 256); vR7[np] = (uint32_t)(row & 7);
    }

    // group 0: Q tile + alibi row
#pragma unroll
    for (int u = 0; u < 16; u++) {
        int idx = tid + 256 * u;
        int r = idx >> 5, c4 = idx & 31;
        uint32_t doff = (uint32_t)((r * 32 + (c4 ^ (r & 7))) * 16);
        asm volatile("cp.async.cg.shared.global [%0], [%1], 16;"
            :: "r"(sQ + doff), "l"(Qg + (size_t)r * 128 + c4 * 4) : "memory");
    }
#pragma unroll
    for (int u = 0; u < 2; u++) {
        int idx = tid + 256 * u;
        asm volatile("cp.async.cg.shared.global [%0], [%1], 16;"
            :: "r"(sAl + idx * 16), "l"(alg + idx * 4) : "memory");
    }
    asm volatile("cp.async.commit_group;" ::: "memory");

#define KV_ISSUE(sbuf, srcp, kb) do { \
    _Pragma("unroll") \
    for (int u = 0; u < 8; u++) { \
        int idx = tid + 256 * u; \
        int r = idx >> 5, c4 = idx & 31; \
        uint32_t doff = (uint32_t)((r * 32 + (c4 ^ (r & 7))) * 16); \
        asm volatile("cp.async.cg.shared.global [%0], [%1], 16;" \
            :: "r"((sbuf) + doff), "l"((srcp) + (size_t)((kb) + r) * 128 + c4 * 4) : "memory"); \
    } \
    asm volatile("cp.async.commit_group;" ::: "memory"); \
} while (0)

    KV_ISSUE(sK0, Kg, 0);

    float o[16][4];
#pragma unroll
    for (int nt = 0; nt < 16; nt++)
#pragma unroll
        for (int q = 0; q < 4; q++) o[nt][q] = 0.f;
    float m0 = -1e30f, m1 = -1e30f, l0 = 0.f, l1 = 0.f;

    const float inv_norm = 0.08838834764831845f;
    const int nT = 2 * qt + 2;
    const int rowg0 = qBase + wid * 16 + g;
    const int rowg1 = rowg0 + 8;

    // V transpose thread mapping: k = tid&63, dblk0 = tid>>6
    const int vk = tid & 63;
    const int vd0 = tid >> 6;

    for (int jt = 0; jt < nT; jt++) {
        const int kB = jt * 64;
        KV_ISSUE(sV, Vg, kB);
        asm volatile("cp.async.wait_group 1;" ::: "memory");   // K[jt] (+Q on jt=0)
        __syncthreads();

        const uint32_t sKc = (jt & 1) ? sK1 : sK0;

        // ---------------- scores: S = Q K^T (16x64 per warp) ----------------
        float s[8][4];
#pragma unroll
        for (int nt = 0; nt < 8; nt++)
#pragma unroll
            for (int q = 0; q < 4; q++) s[nt][q] = 0.f;

#pragma unroll
        for (int k8 = 0; k8 < 16; k8++) {
            uint32_t a[4];
            ldsm4(a, sQ + qAOff + (((2 * k8 + aC) ^ aR7) << 4));
#pragma unroll
            for (int np = 0; np < 4; np++) {
                uint32_t bf[4];
                ldsm4(bf, sKc + kOff[np] + (((2 * k8 + bC) ^ kR7[np]) << 4));
                mma_tf32(s[2 * np],     a, &bf[0]);
                mma_tf32(s[2 * np + 1], a, &bf[2]);
            }
        }

        // prefetch K[jt+1] while V[jt] finishes
        if (jt + 1 < nT) {
            KV_ISSUE((jt & 1) ? sK0 : sK1, Kg, kB + 64);
            asm volatile("cp.async.wait_group 1;" ::: "memory");   // V[jt]
        } else {
            asm volatile("cp.async.wait_group 0;" ::: "memory");
        }
        __syncthreads();

        // ---------------- V in-place transpose: Vs[64][128] -> Vt[128][64] --
        float4 vreg[8];
#pragma unroll
        for (int j = 0; j < 8; j++) {
            int dblk = vd0 + 4 * j;    // 0..31
            vreg[j] = *(const float4*)((const char*)Vs +
                        (size_t)vk * 512 + (((uint32_t)dblk ^ (vk & 7)) << 4));
        }

        // ---------------- scale + alibi + causal mask (register work) -------
        const bool domask = (jt >= 2 * qt);
        float ml0 = -1e30f, ml1 = -1e30f;
#pragma unroll
        for (int nt = 0; nt < 8; nt++) {
            int c0 = kB + nt * 8 + 2 * t;
            float a0 = als[c0], a1 = als[c0 + 1];
            s[nt][0] = s[nt][0] * inv_norm + a0;
            s[nt][1] = s[nt][1] * inv_norm + a1;
            s[nt][2] = s[nt][2] * inv_norm + a0;
            s[nt][3] = s[nt][3] * inv_norm + a1;
            if (domask) {
                if (c0 > rowg0)     s[nt][0] = -1e30f;
                if (c0 + 1 > rowg0) s[nt][1] = -1e30f;
                if (c0 > rowg1)     s[nt][2] = -1e30f;
                if (c0 + 1 > rowg1) s[nt][3] = -1e30f;
            }
            ml0 = fmaxf(ml0, fmaxf(s[nt][0], s[nt][1]));
            ml1 = fmaxf(ml1, fmaxf(s[nt][2], s[nt][3]));
        }
        ml0 = fmaxf(ml0, __shfl_xor_sync(0xffffffffu, ml0, 1));
        ml0 = fmaxf(ml0, __shfl_xor_sync(0xffffffffu, ml0, 2));
        ml1 = fmaxf(ml1, __shfl_xor_sync(0xffffffffu, ml1, 1));
        ml1 = fmaxf(ml1, __shfl_xor_sync(0xffffffffu, ml1, 2));

        float mn0 = fmaxf(m0, ml0), mn1 = fmaxf(m1, ml1);
        float alpha0 = __expf(m0 - mn0), alpha1 = __expf(m1 - mn1);
        m0 = mn0; m1 = mn1;

        float ls0 = 0.f, ls1 = 0.f;
#pragma unroll
        for (int nt = 0; nt < 8; nt++) {
            float p0 = __expf(s[nt][0] - mn0);
            float p1 = __expf(s[nt][1] - mn0);
            float p2 = __expf(s[nt][2] - mn1);
            float p3 = __expf(s[nt][3] - mn1);
            ls0 += p0 + p1;
            ls1 += p2 + p3;
            int c = nt * 8 + 2 * t;
            int r0p = wid * 16 + g;
            float* pp0 = &Ps[(r0p * 16 + (((c >> 2) ^ (r0p & 7)))) * 4 + (c & 3)];
            *(float2*)pp0 = make_float2(rna_tf32(p0), rna_tf32(p1));
            int r1p = r0p + 8;
            float* pp1 = &Ps[(r1p * 16 + (((c >> 2) ^ (r1p & 7)))) * 4 + (c & 3)];
            *(float2*)pp1 = make_float2(rna_tf32(p2), rna_tf32(p3));
        }
        ls0 += __shfl_xor_sync(0xffffffffu, ls0, 1);
        ls0 += __shfl_xor_sync(0xffffffffu, ls0, 2);
        ls1 += __shfl_xor_sync(0xffffffffu, ls1, 1);
        ls1 += __shfl_xor_sync(0xffffffffu, ls1, 2);
        l0 = l0 * alpha0 + ls0;
        l1 = l1 * alpha1 + ls1;

#pragma unroll
        for (int nt = 0; nt < 16; nt++) {
            o[nt][0] *= alpha0; o[nt][1] *= alpha0;
            o[nt][2] *= alpha1; o[nt][3] *= alpha1;
        }

        // write transposed V (all reads done; barrier separates read/write)
        __syncthreads();
#pragma unroll
        for (int j = 0; j < 8; j++) {
            int dblk = vd0 + 4 * j;
            const float* vv = (const float*)&vreg[j];
#pragma unroll
            for (int i2 = 0; i2 < 4; i2++) {
                int d = dblk * 4 + i2;
                ((float*)Vs)[(d * 16 + (((vk >> 2) ^ (d & 7)))) * 4 + (vk & 3)] = vv[i2];
            }
        }
        __syncthreads();

        // ---------------- O += P V  (16x128 per warp, k=64) ----------------
#pragma unroll
        for (int k8 = 0; k8 < 8; k8++) {
            uint32_t a[4];
            ldsm4(a, sP + pAOff + (((2 * k8 + aC) ^ aR7) << 4));
#pragma unroll
            for (int np = 0; np < 8; np++) {
                uint32_t bf[4];
                ldsm4(bf, sV + vOff[np] + (((2 * k8 + bC) ^ vR7[np]) << 4));
                mma_tf32(o[2 * np],     a, &bf[0]);
                mma_tf32(o[2 * np + 1], a, &bf[2]);
            }
        }
        __syncthreads();   // Vs/Ps reused next iteration
    }

    // ---------------- normalize + write ctx (tf32-rounded) ----------------
    const float inv0 = 1.f / l0, inv1 = 1.f / l1;
#pragma unroll
    for (int nt = 0; nt < 16; nt++) {
        int d = nh * HD_ + nt * 8 + 2 * t;
        float2 ov0 = { rna_tf32(o[nt][0] * inv0), rna_tf32(o[nt][1] * inv0) };
        float2 ov1 = { rna_tf32(o[nt][2] * inv1), rna_tf32(o[nt][3] * inv1) };
        *(float2*)&g_ctx[((size_t)(b * S_ + rowg0)) * H_ + d] = ov0;
        *(float2*)&g_ctx[((size_t)(b * S_ + rowg1)) * H_ + d] = ov1;
    }
}

extern "C" void kernel_launch(void* const* d_in, const int* in_sizes, int n_in,
                              void* d_out, int out_size)
{
    (void)in_sizes; (void)n_in; (void)out_size;
    const float* hidden   = (const float*)d_in[0];
    const float* residual = (const float*)d_in[1];
    const float* alibi    = (const float*)d_in[2];
    // d_in[3] = attention_mask: deterministic causal triu(k=1), applied analytically
    const float* W_qkv   = (const float*)d_in[4];
    const float* b_qkv   = (const float*)d_in[5];
    const float* W_dense = (const float*)d_in[6];
    const float* b_dense = (const float*)d_in[7];
    float* out = (float*)d_out;

    cudaFuncSetAttribute(gemm_mma_kernel, cudaFuncAttributeMaxDynamicSharedMemorySize, GSMEM);
    cudaFuncSetAttribute(attn_mma_kernel, cudaFuncAttributeMaxDynamicSharedMemorySize, AT_SMEM);

    // 0) round GEMM inputs to tf32 (RNA, unbiased)
    cvt_tf32_kernel<<<(MTOK * H_ / 4 + 255) / 256, 256>>>(hidden, 0, MTOK * H_ / 4);
    cvt_tf32_kernel<<<(NQKV * H_ / 4 + 255) / 256, 256>>>(W_qkv, 1, NQKV * H_ / 4);
    cvt_tf32_kernel<<<(H_ * H_ / 4 + 255) / 256, 256>>>(W_dense, 2, H_ * H_ / 4);

    // 1) QKV projection (mma tf32) + bias + de-interleave scatter (tf32-rounded)
    gemm_mma_kernel<<<dim3(MTOK / 128, NQKV / 256), 256, GSMEM>>>(b_qkv, nullptr, nullptr, 0);

    // 2) causal attention with alibi — tf32 mma + ldmatrix flash kernel
    attn_mma_kernel<<<dim3(B_ * NH_, S_ / 128), 256, AT_SMEM>>>(alibi);

    // 3) dense projection (mma tf32) + bias + residual
    gemm_mma_kernel<<<dim3(MTOK / 128, H_ / 256), 256, GSMEM>>>(b_dense, residual, out, 1);
}

// round 9
// speedup vs baseline: 5.3853x; 1.1725x over previous
#include <cuda_runtime.h>
#include <cstdint>

#define B_ 2
#define S_ 2048
#define H_ 4096
#define NH_ 32
#define HD_ 128
#define MTOK (B_ * S_)
#define NQKV (3 * H_)
#define ELEMS (B_ * NH_ * S_ * HD_)

// ---------------- scratch (device globals: allocation-free) ----------------
__device__ float g_Q[ELEMS];
__device__ float g_K[ELEMS];
__device__ float g_V[ELEMS];          // stored TRANSPOSED: [b][nh][d][s]
__device__ float g_ctx[(size_t)MTOK * H_];
__device__ float g_Ar[(size_t)MTOK * H_];
__device__ float g_Wq[(size_t)NQKV * H_];
__device__ float g_Wd[(size_t)H_ * H_];

__device__ __forceinline__ uint32_t smem_u32(const void* p) {
    uint32_t a;
    asm("{ .reg .u64 t; cvta.to.shared.u64 t, %1; cvt.u32.u64 %0, t; }" : "=r"(a) : "l"(p));
    return a;
}
__device__ __forceinline__ float rna_tf32(float x) {
    uint32_t u;
    asm("cvt.rna.tf32.f32 %0, %1;" : "=r"(u) : "f"(x));
    return __uint_as_float(u);
}
__device__ __forceinline__ void ldsm4(uint32_t* r, uint32_t addr) {
    asm volatile("ldmatrix.sync.aligned.m8n8.x4.shared.b16 {%0,%1,%2,%3}, [%4];"
        : "=r"(r[0]), "=r"(r[1]), "=r"(r[2]), "=r"(r[3]) : "r"(addr));
}
__device__ __forceinline__ void mma_tf32(float* c, const uint32_t* a, const uint32_t* b) {
    asm volatile("mma.sync.aligned.m16n8k8.row.col.f32.tf32.tf32.f32 "
        "{%0,%1,%2,%3}, {%4,%5,%6,%7}, {%8,%9}, {%0,%1,%2,%3};"
        : "+f"(c[0]), "+f"(c[1]), "+f"(c[2]), "+f"(c[3])
        : "r"(a[0]), "r"(a[1]), "r"(a[2]), "r"(a[3]), "r"(b[0]), "r"(b[1]));
}

// ---------------- tf32 round-to-nearest conversion ----------------
__global__ __launch_bounds__(256)
void cvt_tf32_kernel(const float* __restrict__ src, int which, int n4)
{
    float* dst = (which == 0) ? g_Ar : (which == 1) ? g_Wq : g_Wd;
    int i = blockIdx.x * 256 + threadIdx.x;
    if (i >= n4) return;
    float4 v = ((const float4*)src)[i];
    float4 o;
    o.x = rna_tf32(v.x); o.y = rna_tf32(v.y);
    o.z = rna_tf32(v.z); o.w = rna_tf32(v.w);
    ((float4*)dst)[i] = o;
}

// ============== mma.sync tf32 GEMM, 128x128 tiles, 2 CTAs/SM ===============
#define KCH 32
#define ASZB (128 * KCH * 4)      /* 16384 */
#define STG  (2 * ASZB)           /* 32768 */
#define NSTG 3
#define GSMEM (NSTG * STG)        /* 98304 -> 2 CTAs/SM */

__global__ __launch_bounds__(256, 2)
void gemm_mma_kernel(const float* __restrict__ bias, const float* __restrict__ resid,
                     float* __restrict__ out, int mode)
{
    extern __shared__ char smraw[];
    const uint32_t sbase = smem_u32(smraw);

    const int tid = threadIdx.x;
    const int wid = tid >> 5;
    const int lane = tid & 31;
    const int g = lane >> 2, t = lane & 3;
    const int lr = lane & 7;
    const int lm = lane >> 3;
    const int warpM = wid >> 2;     // 0..1 (64 rows)
    const int warpN = wid & 3;      // 0..3 (32 cols)
    const int mBase = blockIdx.x * 128;
    const int nBase = blockIdx.y * 128;
    const int K = H_;
    const int nk = K / KCH;

    const float* Asrc = mode ? (const float*)g_ctx : (const float*)g_Ar;
    const float* Wsrc = mode ? (const float*)g_Wd  : (const float*)g_Wq;

    // loader: A and B each 128 rows x 8 float4/chunk; thread handles 4 rows apart by 32
    const int ldRow = tid >> 3;          // 0..31
    const int ldC4  = tid & 7;
    const float* srcA = Asrc + (size_t)(mBase + ldRow) * K + ldC4 * 4;
    const float* srcB = Wsrc + (size_t)(nBase + ldRow) * K + ldC4 * 4;
    const uint32_t dA = (uint32_t)(ldRow * 128 + ((ldC4 ^ (ldRow & 7)) << 4));
    const uint32_t dB = dA + ASZB;

    // ldmatrix row precompute
    uint32_t aOff[4], aR7[4];
#pragma unroll
    for (int mt = 0; mt < 4; mt++) {
        int row = warpM * 64 + mt * 16 + lr + ((lm & 1) << 3);
        aOff[mt] = (uint32_t)(row * 128); aR7[mt] = (uint32_t)(row & 7);
    }
    uint32_t bOff[2], bR7[2];
#pragma unroll
    for (int np = 0; np < 2; np++) {
        int row = warpN * 32 + np * 16 + lr + ((lm >> 1) << 3);
        bOff[np] = (uint32_t)(ASZB + row * 128); bR7[np] = (uint32_t)(row & 7);
    }
    const uint32_t aC = (uint32_t)(lm >> 1);
    const uint32_t bC = (uint32_t)(lm & 1);

    float acc[4][4][4];
#pragma unroll
    for (int mt = 0; mt < 4; mt++)
#pragma unroll
        for (int nt = 0; nt < 4; nt++)
#pragma unroll
            for (int q = 0; q < 4; q++) acc[mt][nt][q] = 0.f;

#define ISSUE(i) do { \
    uint32_t sb_ = sbase + ((i) % NSTG) * STG; \
    _Pragma("unroll") \
    for (int u = 0; u < 4; u++) \
        asm volatile("cp.async.cg.shared.global [%0], [%1], 16;" \
            :: "r"(sb_ + dA + 4096u * u), "l"(srcA + (size_t)(i) * KCH + (size_t)(32 * u) * K) : "memory"); \
    _Pragma("unroll") \
    for (int u = 0; u < 4; u++) \
        asm volatile("cp.async.cg.shared.global [%0], [%1], 16;" \
            :: "r"(sb_ + dB + 4096u * u), "l"(srcB + (size_t)(i) * KCH + (size_t)(32 * u) * K) : "memory"); \
    asm volatile("cp.async.commit_group;" ::: "memory"); \
} while (0)

    ISSUE(0);
    ISSUE(1);

    for (int i = 0; i < nk; i++) {
        if (i < nk - 1)
            asm volatile("cp.async.wait_group 1;" ::: "memory");
        else
            asm volatile("cp.async.wait_group 0;" ::: "memory");
        __syncthreads();
        if (i + 2 < nk) ISSUE(i + 2);

        const uint32_t sst = sbase + (i % NSTG) * STG;
#pragma unroll
        for (int k8 = 0; k8 < 4; k8++) {
            const uint32_t ac4 = 2 * k8 + aC;
            const uint32_t bc4 = 2 * k8 + bC;
            uint32_t Af[4][4], Bf[2][4];
#pragma unroll
            for (int mt = 0; mt < 4; mt++)
                ldsm4(Af[mt], sst + aOff[mt] + ((ac4 ^ aR7[mt]) << 4));
#pragma unroll
            for (int np = 0; np < 2; np++)
                ldsm4(Bf[np], sst + bOff[np] + ((bc4 ^ bR7[np]) << 4));
#pragma unroll
            for (int mt = 0; mt < 4; mt++)
#pragma unroll
                for (int np = 0; np < 2; np++) {
                    mma_tf32(acc[mt][2 * np],     Af[mt], &Bf[np][0]);
                    mma_tf32(acc[mt][2 * np + 1], Af[mt], &Bf[np][2]);
                }
        }
    }

    // ------------------------- epilogue -------------------------
#pragma unroll
    for (int mt = 0; mt < 4; mt++) {
        int r0 = mBase + warpM * 64 + mt * 16 + g;
#pragma unroll
        for (int nt = 0; nt < 4; nt++) {
            int o = nBase + warpN * 32 + nt * 8 + t * 2;
            float2 bi = *(const float2*)&bias[o];
            if (mode == 0) {
                int nh  = o / 384;
                int rem = o - nh * 384;
                int tt  = rem >> 7;
                int d   = rem & 127;
                int bb  = r0 >> 11;
                int s0  = r0 & 2047;
                int s1  = (r0 + 8) & 2047;
                float v0 = rna_tf32(acc[mt][nt][0] + bi.x);
                float v1 = rna_tf32(acc[mt][nt][1] + bi.y);
                float v2 = rna_tf32(acc[mt][nt][2] + bi.x);
                float v3 = rna_tf32(acc[mt][nt][3] + bi.y);
                if (tt == 2) {
                    // V transposed: [b][nh][d][s]
                    size_t vb = ((size_t)bb * NH_ + nh) * HD_;
                    g_V[(vb + d)     * S_ + s0] = v0;
                    g_V[(vb + d + 1) * S_ + s0] = v1;
                    g_V[(vb + d)     * S_ + s1] = v2;
                    g_V[(vb + d + 1) * S_ + s1] = v3;
                } else {
                    float* dstg = (tt == 0) ? g_Q : g_K;
                    size_t rb = (((size_t)bb * NH_ + nh) * S_);
                    *(float2*)&dstg[(rb + s0) * HD_ + d] = make_float2(v0, v1);
                    *(float2*)&dstg[(rb + s1) * HD_ + d] = make_float2(v2, v3);
                }
            } else {
                {
                    float2 rs = *(const float2*)&resid[(size_t)r0 * H_ + o];
                    float2 ov = { acc[mt][nt][0] + bi.x + rs.x, acc[mt][nt][1] + bi.y + rs.y };
                    *(float2*)&out[(size_t)r0 * H_ + o] = ov;
                }
                {
                    int r1 = r0 + 8;
                    float2 rs = *(const float2*)&resid[(size_t)r1 * H_ + o];
                    float2 ov = { acc[mt][nt][2] + bi.x + rs.x, acc[mt][nt][3] + bi.y + rs.y };
                    *(float2*)&out[(size_t)r1 * H_ + o] = ov;
                }
            }
        }
    }
}

// ============ flash attention: tf32 mma + ldmatrix, pre-transposed V =======
#define AT_SMEM ((128 * 128 + 2 * 64 * 128 + 128 * 64 + 128 * 64 + 2048) * 4)  /* 196608 */

__global__ __launch_bounds__(256, 1)
void attn_mma_kernel(const float* __restrict__ alibi)
{
    extern __shared__ float sm[];
    float* Qs  = sm;                       // 128 x 128 (512B rows, swizzled)
    float* Ks0 = Qs  + 128 * 128;          // 64 x 128
    float* Ks1 = Ks0 + 64 * 128;           // 64 x 128
    float* Vs  = Ks1 + 64 * 128;           // 128 x 64 (Vt tile, 256B rows)
    float* Ps  = Vs  + 128 * 64;           // 128 x 64 (256B rows, swizzled)
    float* als = Ps  + 128 * 64;           // 2048

    const int tid = threadIdx.x;
    const int wid = tid >> 5;
    const int lane = tid & 31;
    const int g = lane >> 2, t = lane & 3;
    const int lr = lane & 7;
    const int lm = lane >> 3;
    const int bh = blockIdx.x;
    const int qt = (int)gridDim.y - 1 - (int)blockIdx.y;
    const int b = bh >> 5, nh = bh & 31;
    const int qBase = qt * 128;

    const float* Qg  = g_Q + (size_t)bh * S_ * HD_ + (size_t)qBase * HD_;
    const float* Kg  = g_K + (size_t)bh * S_ * HD_;
    const float* Vg  = g_V + (size_t)bh * S_ * HD_;   // [d][s] within head
    const float* alg = alibi + (size_t)bh * S_;

    const uint32_t sQ  = smem_u32(Qs);
    const uint32_t sK0 = smem_u32(Ks0);
    const uint32_t sK1 = smem_u32(Ks1);
    const uint32_t sV  = smem_u32(Vs);
    const uint32_t sP  = smem_u32(Ps);
    const uint32_t sAl = smem_u32(als);

    const uint32_t aC = (uint32_t)(lm >> 1);
    const uint32_t bC = (uint32_t)(lm & 1);
    const int aRow = wid * 16 + lr + ((lm & 1) << 3);
    const uint32_t aR7 = (uint32_t)(aRow & 7);
    const uint32_t qAOff = (uint32_t)(aRow * 512);
    const uint32_t pAOff = (uint32_t)(aRow * 256);
    uint32_t kOff[4], kR7[4];
#pragma unroll
    for (int np = 0; np < 4; np++) {
        int row = np * 16 + lr + ((lm >> 1) << 3);
        kOff[np] = (uint32_t)(row * 512); kR7[np] = (uint32_t)(row & 7);
    }
    uint32_t vOff[8], vR7[8];
#pragma unroll
    for (int np = 0; np < 8; np++) {
        int row = np * 16 + lr + ((lm >> 1) << 3);
        vOff[np] = (uint32_t)(row * 256); vR7[np] = (uint32_t)(row & 7);
    }

    // group 0: Q tile + alibi row
#pragma unroll
    for (int u = 0; u < 16; u++) {
        int idx = tid + 256 * u;
        int r = idx >> 5, c4 = idx & 31;
        uint32_t doff = (uint32_t)((r * 32 + (c4 ^ (r & 7))) * 16);
        asm volatile("cp.async.cg.shared.global [%0], [%1], 16;"
            :: "r"(sQ + doff), "l"(Qg + (size_t)r * 128 + c4 * 4) : "memory");
    }
#pragma unroll
    for (int u = 0; u < 2; u++) {
        int idx = tid + 256 * u;
        asm volatile("cp.async.cg.shared.global [%0], [%1], 16;"
            :: "r"(sAl + idx * 16), "l"(alg + idx * 4) : "memory");
    }
    asm volatile("cp.async.commit_group;" ::: "memory");

// K tile: 64 rows(s) x 128 cols(d), 512B rows
#define K_ISSUE(sbuf, kb) do { \
    _Pragma("unroll") \
    for (int u = 0; u < 8; u++) { \
        int idx = tid + 256 * u; \
        int r = idx >> 5, c4 = idx & 31; \
        uint32_t doff = (uint32_t)((r * 32 + (c4 ^ (r & 7))) * 16); \
        asm volatile("cp.async.cg.shared.global [%0], [%1], 16;" \
            :: "r"((sbuf) + doff), "l"(Kg + (size_t)((kb) + r) * 128 + c4 * 4) : "memory"); \
    } \
    asm volatile("cp.async.commit_group;" ::: "memory"); \
} while (0)

// Vt tile: 128 rows(d) x 64 cols(s), 256B rows
#define VT_ISSUE(kb) do { \
    _Pragma("unroll") \
    for (int u = 0; u < 8; u++) { \
        int idx = tid + 256 * u; \
        int r = idx >> 4, c4 = idx & 15; \
        uint32_t doff = (uint32_t)((r * 16 + (c4 ^ (r & 7))) * 16); \
        asm volatile("cp.async.cg.shared.global [%0], [%1], 16;" \
            :: "r"(sV + doff), "l"(Vg + (size_t)r * S_ + (kb) + c4 * 4) : "memory"); \
    } \
    asm volatile("cp.async.commit_group;" ::: "memory"); \
} while (0)

    K_ISSUE(sK0, 0);

    float o[16][4];
#pragma unroll
    for (int nt = 0; nt < 16; nt++)
#pragma unroll
        for (int q = 0; q < 4; q++) o[nt][q] = 0.f;
    float m0 = -1e30f, m1 = -1e30f, l0 = 0.f, l1 = 0.f;

    const float inv_norm = 0.08838834764831845f;
    const int nT = 2 * qt + 2;
    const int rowg0 = qBase + wid * 16 + g;
    const int rowg1 = rowg0 + 8;

    for (int jt = 0; jt < nT; jt++) {
        const int kB = jt * 64;
        // wait everything outstanding (K[jt] is the newest); barrier also makes
        // it safe to overwrite Vs (all warps finished PV of jt-1)
        asm volatile("cp.async.wait_group 0;" ::: "memory");
        __syncthreads();
        VT_ISSUE(kB);                               // V[jt] overlaps QK compute

        const uint32_t sKc = (jt & 1) ? sK1 : sK0;

        // ---------------- scores: S = Q K^T (16x64 per warp) ----------------
        float s[8][4];
#pragma unroll
        for (int nt = 0; nt < 8; nt++)
#pragma unroll
            for (int q = 0; q < 4; q++) s[nt][q] = 0.f;

#pragma unroll
        for (int k8 = 0; k8 < 16; k8++) {
            uint32_t a[4];
            ldsm4(a, sQ + qAOff + (((2 * k8 + aC) ^ aR7) << 4));
#pragma unroll
            for (int np = 0; np < 4; np++) {
                uint32_t bf[4];
                ldsm4(bf, sKc + kOff[np] + (((2 * k8 + bC) ^ kR7[np]) << 4));
                mma_tf32(s[2 * np],     a, &bf[0]);
                mma_tf32(s[2 * np + 1], a, &bf[2]);
            }
        }

        // prefetch K[jt+1]; wait V[jt] (newest is K[jt+1] -> wait_group 1)
        if (jt + 1 < nT) {
            K_ISSUE((jt & 1) ? sK0 : sK1, kB + 64);
            asm volatile("cp.async.wait_group 1;" ::: "memory");
        } else {
            asm volatile("cp.async.wait_group 0;" ::: "memory");
        }

        // ---------------- scale + alibi + causal mask ----------------
        const bool domask = (jt >= 2 * qt);
        float ml0 = -1e30f, ml1 = -1e30f;
#pragma unroll
        for (int nt = 0; nt < 8; nt++) {
            int c0 = kB + nt * 8 + 2 * t;
            float a0 = als[c0], a1 = als[c0 + 1];
            s[nt][0] = s[nt][0] * inv_norm + a0;
            s[nt][1] = s[nt][1] * inv_norm + a1;
            s[nt][2] = s[nt][2] * inv_norm + a0;
            s[nt][3] = s[nt][3] * inv_norm + a1;
            if (domask) {
                if (c0 > rowg0)     s[nt][0] = -1e30f;
                if (c0 + 1 > rowg0) s[nt][1] = -1e30f;
                if (c0 > rowg1)     s[nt][2] = -1e30f;
                if (c0 + 1 > rowg1) s[nt][3] = -1e30f;
            }
            ml0 = fmaxf(ml0, fmaxf(s[nt][0], s[nt][1]));
            ml1 = fmaxf(ml1, fmaxf(s[nt][2], s[nt][3]));
        }
        ml0 = fmaxf(ml0, __shfl_xor_sync(0xffffffffu, ml0, 1));
        ml0 = fmaxf(ml0, __shfl_xor_sync(0xffffffffu, ml0, 2));
        ml1 = fmaxf(ml1, __shfl_xor_sync(0xffffffffu, ml1, 1));
        ml1 = fmaxf(ml1, __shfl_xor_sync(0xffffffffu, ml1, 2));

        float mn0 = fmaxf(m0, ml0), mn1 = fmaxf(m1, ml1);
        float alpha0 = __expf(m0 - mn0), alpha1 = __expf(m1 - mn1);
        m0 = mn0; m1 = mn1;

        float ls0 = 0.f, ls1 = 0.f;
#pragma unroll
        for (int nt = 0; nt < 8; nt++) {
            float p0 = __expf(s[nt][0] - mn0);
            float p1 = __expf(s[nt][1] - mn0);
            float p2 = __expf(s[nt][2] - mn1);
            float p3 = __expf(s[nt][3] - mn1);
            ls0 += p0 + p1;
            ls1 += p2 + p3;
            int c = nt * 8 + 2 * t;
            int r0p = wid * 16 + g;
            float* pp0 = &Ps[(r0p * 16 + (((c >> 2) ^ (r0p & 7)))) * 4 + (c & 3)];
            *(float2*)pp0 = make_float2(rna_tf32(p0), rna_tf32(p1));
            int r1p = r0p + 8;
            float* pp1 = &Ps[(r1p * 16 + (((c >> 2) ^ (r1p & 7)))) * 4 + (c & 3)];
            *(float2*)pp1 = make_float2(rna_tf32(p2), rna_tf32(p3));
        }
        ls0 += __shfl_xor_sync(0xffffffffu, ls0, 1);
        ls0 += __shfl_xor_sync(0xffffffffu, ls0, 2);
        ls1 += __shfl_xor_sync(0xffffffffu, ls1, 1);
        ls1 += __shfl_xor_sync(0xffffffffu, ls1, 2);
        l0 = l0 * alpha0 + ls0;
        l1 = l1 * alpha1 + ls1;

#pragma unroll
        for (int nt = 0; nt < 16; nt++) {
            o[nt][0] *= alpha0; o[nt][1] *= alpha0;
            o[nt][2] *= alpha1; o[nt][3] *= alpha1;
        }

        __syncthreads();   // all warps' V cp.asyncs visible before PV

        // ---------------- O += P V  (16x128 per warp, k=64) ----------------
#pragma unroll
        for (int k8 = 0; k8 < 8; k8++) {
            uint32_t a[4];
            ldsm4(a, sP + pAOff + (((2 * k8 + aC) ^ aR7) << 4));
#pragma unroll
            for (int np = 0; np < 8; np++) {
                uint32_t bf[4];
                ldsm4(bf, sV + vOff[np] + (((2 * k8 + bC) ^ vR7[np]) << 4));
                mma_tf32(o[2 * np],     a, &bf[0]);
                mma_tf32(o[2 * np + 1], a, &bf[2]);
            }
        }
        // no end barrier: next iteration's top wait_group 0 + __syncthreads
        // covers Vs overwrite safety
    }

    // ---------------- normalize + write ctx (tf32-rounded) ----------------
    const float inv0 = 1.f / l0, inv1 = 1.f / l1;
#pragma unroll
    for (int nt = 0; nt < 16; nt++) {
        int d = nh * HD_ + nt * 8 + 2 * t;
        float2 ov0 = { rna_tf32(o[nt][0] * inv0), rna_tf32(o[nt][1] * inv0) };
        float2 ov1 = { rna_tf32(o[nt][2] * inv1), rna_tf32(o[nt][3] * inv1) };
        *(float2*)&g_ctx[((size_t)(b * S_ + rowg0)) * H_ + d] = ov0;
        *(float2*)&g_ctx[((size_t)(b * S_ + rowg1)) * H_ + d] = ov1;
    }
}

extern "C" void kernel_launch(void* const* d_in, const int* in_sizes, int n_in,
                              void* d_out, int out_size)
{
    (void)in_sizes; (void)n_in; (void)out_size;
    const float* hidden   = (const float*)d_in[0];
    const float* residual = (const float*)d_in[1];
    const float* alibi    = (const float*)d_in[2];
    // d_in[3] = attention_mask: deterministic causal triu(k=1), applied analytically
    const float* W_qkv   = (const float*)d_in[4];
    const float* b_qkv   = (const float*)d_in[5];
    const float* W_dense = (const float*)d_in[6];
    const float* b_dense = (const float*)d_in[7];
    float* out = (float*)d_out;

    cudaFuncSetAttribute(gemm_mma_kernel, cudaFuncAttributeMaxDynamicSharedMemorySize, GSMEM);
    cudaFuncSetAttribute(attn_mma_kernel, cudaFuncAttributeMaxDynamicSharedMemorySize, AT_SMEM);

    // 0) round GEMM inputs to tf32 (RNA, unbiased)
    cvt_tf32_kernel<<<(MTOK * H_ / 4 + 255) / 256, 256>>>(hidden, 0, MTOK * H_ / 4);
    cvt_tf32_kernel<<<(NQKV * H_ / 4 + 255) / 256, 256>>>(W_qkv, 1, NQKV * H_ / 4);
    cvt_tf32_kernel<<<(H_ * H_ / 4 + 255) / 256, 256>>>(W_dense, 2, H_ * H_ / 4);

    // 1) QKV projection + bias + de-interleave scatter (V pre-transposed)
    gemm_mma_kernel<<<dim3(MTOK / 128, NQKV / 128), 256, GSMEM>>>(b_qkv, nullptr, nullptr, 0);

    // 2) causal attention with alibi — tf32 mma + ldmatrix flash kernel
    attn_mma_kernel<<<dim3(B_ * NH_, S_ / 128), 256, AT_SMEM>>>(alibi);

    // 3) dense projection + bias + residual
    gemm_mma_kernel<<<dim3(MTOK / 128, H_ / 128), 256, GSMEM>>>(b_dense, residual, out, 1);
}

// round 11
// speedup vs baseline: 5.3988x; 1.0025x over previous
#include <cuda_runtime.h>
#include <cstdint>

#define B_ 2
#define S_ 2048
#define H_ 4096
#define NH_ 32
#define HD_ 128
#define MTOK (B_ * S_)
#define NQKV (3 * H_)
#define ELEMS (B_ * NH_ * S_ * HD_)

// ---------------- scratch (device globals: allocation-free) ----------------
__device__ float g_Q[ELEMS];
__device__ float g_K[ELEMS];
__device__ float g_V[ELEMS];          // stored TRANSPOSED: [b][nh][d][s]
__device__ float g_ctx[(size_t)MTOK * H_];
__device__ float g_Ar[(size_t)MTOK * H_];
__device__ float g_Wq[(size_t)NQKV * H_];
__device__ float g_Wd[(size_t)H_ * H_];

__device__ __forceinline__ uint32_t smem_u32(const void* p) {
    uint32_t a;
    asm("{ .reg .u64 t; cvta.to.shared.u64 t, %1; cvt.u32.u64 %0, t; }" : "=r"(a) : "l"(p));
    return a;
}
__device__ __forceinline__ float rna_tf32(float x) {
    uint32_t u;
    asm("cvt.rna.tf32.f32 %0, %1;" : "=r"(u) : "f"(x));
    return __uint_as_float(u);
}
__device__ __forceinline__ void ldsm4(uint32_t* r, uint32_t addr) {
    asm volatile("ldmatrix.sync.aligned.m8n8.x4.shared.b16 {%0,%1,%2,%3}, [%4];"
        : "=r"(r[0]), "=r"(r[1]), "=r"(r[2]), "=r"(r[3]) : "r"(addr));
}
__device__ __forceinline__ void mma_tf32(float* c, const uint32_t* a, const uint32_t* b) {
    asm volatile("mma.sync.aligned.m16n8k8.row.col.f32.tf32.tf32.f32 "
        "{%0,%1,%2,%3}, {%4,%5,%6,%7}, {%8,%9}, {%0,%1,%2,%3};"
        : "+f"(c[0]), "+f"(c[1]), "+f"(c[2]), "+f"(c[3])
        : "r"(a[0]), "r"(a[1]), "r"(a[2]), "r"(a[3]), "r"(b[0]), "r"(b[1]));
}

// ---------------- tf32 round-to-nearest conversion ----------------
__global__ __launch_bounds__(256)
void cvt_tf32_kernel(const float* __restrict__ src, int which, int n4)
{
    float* dst = (which == 0) ? g_Ar : (which == 1) ? g_Wq : g_Wd;
    int i = blockIdx.x * 256 + threadIdx.x;
    if (i >= n4) return;
    float4 v = ((const float4*)src)[i];
    float4 o;
    o.x = rna_tf32(v.x); o.y = rna_tf32(v.y);
    o.z = rna_tf32(v.z); o.w = rna_tf32(v.w);
    ((float4*)dst)[i] = o;
}

// ============== mma.sync tf32 GEMM, 128x128 tiles, 2 CTAs/SM ===============
#define KCH 32
#define ASZB (128 * KCH * 4)      /* 16384 */
#define STG  (2 * ASZB)           /* 32768 */
#define NSTG 3
#define GSMEM (NSTG * STG)        /* 98304 -> 2 CTAs/SM */

__global__ __launch_bounds__(256, 2)
void gemm_mma_kernel(const float* __restrict__ bias, const float* __restrict__ resid,
                     float* __restrict__ out, int mode)
{
    extern __shared__ char smraw[];
    const uint32_t sbase = smem_u32(smraw);

    const int tid = threadIdx.x;
    const int wid = tid >> 5;
    const int lane = tid & 31;
    const int g = lane >> 2, t = lane & 3;
    const int lr = lane & 7;
    const int lm = lane >> 3;
    const int warpM = wid >> 2;     // 0..1 (64 rows)
    const int warpN = wid & 3;      // 0..3 (32 cols)
    const int mBase = blockIdx.x * 128;
    const int nBase = blockIdx.y * 128;
    const int K = H_;
    const int nk = K / KCH;

    const float* Asrc = mode ? (const float*)g_ctx : (const float*)g_Ar;
    const float* Wsrc = mode ? (const float*)g_Wd  : (const float*)g_Wq;

    const int ldRow = tid >> 3;          // 0..31
    const int ldC4  = tid & 7;
    const float* srcA = Asrc + (size_t)(mBase + ldRow) * K + ldC4 * 4;
    const float* srcB = Wsrc + (size_t)(nBase + ldRow) * K + ldC4 * 4;
    const uint32_t dA = (uint32_t)(ldRow * 128 + ((ldC4 ^ (ldRow & 7)) << 4));
    const uint32_t dB = dA + ASZB;

    uint32_t aOff[4], aR7[4];
#pragma unroll
    for (int mt = 0; mt < 4; mt++) {
        int row = warpM * 64 + mt * 16 + lr + ((lm & 1) << 3);
        aOff[mt] = (uint32_t)(row * 128); aR7[mt] = (uint32_t)(row & 7);
    }
    uint32_t bOff[2], bR7[2];
#pragma unroll
    for (int np = 0; np < 2; np++) {
        int row = warpN * 32 + np * 16 + lr + ((lm >> 1) << 3);
        bOff[np] = (uint32_t)(ASZB + row * 128); bR7[np] = (uint32_t)(row & 7);
    }
    const uint32_t aC = (uint32_t)(lm >> 1);
    const uint32_t bC = (uint32_t)(lm & 1);

    float acc[4][4][4];
#pragma unroll
    for (int mt = 0; mt < 4; mt++)
#pragma unroll
        for (int nt = 0; nt < 4; nt++)
#pragma unroll
            for (int q = 0; q < 4; q++) acc[mt][nt][q] = 0.f;

#define ISSUE(i) do { \
    uint32_t sb_ = sbase + ((i) % NSTG) * STG; \
    _Pragma("unroll") \
    for (int u = 0; u < 4; u++) \
        asm volatile("cp.async.cg.shared.global [%0], [%1], 16;" \
            :: "r"(sb_ + dA + 4096u * u), "l"(srcA + (size_t)(i) * KCH + (size_t)(32 * u) * K) : "memory"); \
    _Pragma("unroll") \
    for (int u = 0; u < 4; u++) \
        asm volatile("cp.async.cg.shared.global [%0], [%1], 16;" \
            :: "r"(sb_ + dB + 4096u * u), "l"(srcB + (size_t)(i) * KCH + (size_t)(32 * u) * K) : "memory"); \
    asm volatile("cp.async.commit_group;" ::: "memory"); \
} while (0)

    ISSUE(0);
    ISSUE(1);

    for (int i = 0; i < nk; i++) {
        if (i < nk - 1)
            asm volatile("cp.async.wait_group 1;" ::: "memory");
        else
            asm volatile("cp.async.wait_group 0;" ::: "memory");
        __syncthreads();
        if (i + 2 < nk) ISSUE(i + 2);

        const uint32_t sst = sbase + (i % NSTG) * STG;
#pragma unroll
        for (int k8 = 0; k8 < 4; k8++) {
            const uint32_t ac4 = 2 * k8 + aC;
            const uint32_t bc4 = 2 * k8 + bC;
            uint32_t Af[4][4], Bf[2][4];
#pragma unroll
            for (int mt = 0; mt < 4; mt++)
                ldsm4(Af[mt], sst + aOff[mt] + ((ac4 ^ aR7[mt]) << 4));
#pragma unroll
            for (int np = 0; np < 2; np++)
                ldsm4(Bf[np], sst + bOff[np] + ((bc4 ^ bR7[np]) << 4));
#pragma unroll
            for (int mt = 0; mt < 4; mt++)
#pragma unroll
                for (int np = 0; np < 2; np++) {
                    mma_tf32(acc[mt][2 * np],     Af[mt], &Bf[np][0]);
                    mma_tf32(acc[mt][2 * np + 1], Af[mt], &Bf[np][2]);
                }
        }
    }

    // ------------------------- epilogue -------------------------
#pragma unroll
    for (int mt = 0; mt < 4; mt++) {
        int r0 = mBase + warpM * 64 + mt * 16 + g;
#pragma unroll
        for (int nt = 0; nt < 4; nt++) {
            int o = nBase + warpN * 32 + nt * 8 + t * 2;
            float2 bi = *(const float2*)&bias[o];
            if (mode == 0) {
                int nh  = o / 384;
                int rem = o - nh * 384;
                int tt  = rem >> 7;
                int d   = rem & 127;
                int bb  = r0 >> 11;
                int s0  = r0 & 2047;
                int s1  = (r0 + 8) & 2047;
                float v0 = rna_tf32(acc[mt][nt][0] + bi.x);
                float v1 = rna_tf32(acc[mt][nt][1] + bi.y);
                float v2 = rna_tf32(acc[mt][nt][2] + bi.x);
                float v3 = rna_tf32(acc[mt][nt][3] + bi.y);
                if (tt == 2) {
                    size_t vb = ((size_t)bb * NH_ + nh) * HD_;
                    g_V[(vb + d)     * S_ + s0] = v0;
                    g_V[(vb + d + 1) * S_ + s0] = v1;
                    g_V[(vb + d)     * S_ + s1] = v2;
                    g_V[(vb + d + 1) * S_ + s1] = v3;
                } else {
                    float* dstg = (tt == 0) ? g_Q : g_K;
                    size_t rb = (((size_t)bb * NH_ + nh) * S_);
                    *(float2*)&dstg[(rb + s0) * HD_ + d] = make_float2(v0, v1);
                    *(float2*)&dstg[(rb + s1) * HD_ + d] = make_float2(v2, v3);
                }
            } else {
                {
                    float2 rs = *(const float2*)&resid[(size_t)r0 * H_ + o];
                    float2 ov = { acc[mt][nt][0] + bi.x + rs.x, acc[mt][nt][1] + bi.y + rs.y };
                    *(float2*)&out[(size_t)r0 * H_ + o] = ov;
                }
                {
                    int r1 = r0 + 8;
                    float2 rs = *(const float2*)&resid[(size_t)r1 * H_ + o];
                    float2 ov = { acc[mt][nt][2] + bi.x + rs.x, acc[mt][nt][3] + bi.y + rs.y };
                    *(float2*)&out[(size_t)r1 * H_ + o] = ov;
                }
            }
        }
    }
}

// ============ flash attention: tf32 mma + ldmatrix, double-buffered K & V ==
// one barrier + one wait per k-tile; alibi read straight from global (L1)
#define AT_SMEM ((128 * 128 + 2 * 64 * 128 + 2 * 128 * 64 + 128 * 64) * 4)  /* 229376 */

__global__ __launch_bounds__(256, 1)
void attn_mma_kernel(const float* __restrict__ alibi)
{
    extern __shared__ float sm[];
    float* Qs  = sm;                       // 128 x 128 (512B rows, swizzled)
    float* Ks0 = Qs  + 128 * 128;          // 64 x 128
    float* Ks1 = Ks0 + 64 * 128;           // 64 x 128
    float* Vs0 = Ks1 + 64 * 128;           // 128 x 64 (Vt tile, 256B rows)
    float* Vs1 = Vs0 + 128 * 64;           // 128 x 64
    float* Ps  = Vs1 + 128 * 64;           // 128 x 64

    const int tid = threadIdx.x;
    const int wid = tid >> 5;
    const int lane = tid & 31;
    const int g = lane >> 2, t = lane & 3;
    const int lr = lane & 7;
    const int lm = lane >> 3;
    const int bh = blockIdx.x;
    const int qt = (int)gridDim.y - 1 - (int)blockIdx.y;
    const int b = bh >> 5, nh = bh & 31;
    const int qBase = qt * 128;

    const float* Qg  = g_Q + (size_t)bh * S_ * HD_ + (size_t)qBase * HD_;
    const float* Kg  = g_K + (size_t)bh * S_ * HD_;
    const float* Vg  = g_V + (size_t)bh * S_ * HD_;   // [d][s] within head
    const float* alg = alibi + (size_t)bh * S_;

    const uint32_t sQ  = smem_u32(Qs);
    const uint32_t sK0 = smem_u32(Ks0);
    const uint32_t sK1 = smem_u32(Ks1);
    const uint32_t sV0 = smem_u32(Vs0);
    const uint32_t sV1 = smem_u32(Vs1);
    const uint32_t sP  = smem_u32(Ps);

    const uint32_t aC = (uint32_t)(lm >> 1);
    const uint32_t bC = (uint32_t)(lm & 1);
    const int aRow = wid * 16 + lr + ((lm & 1) << 3);
    const uint32_t aR7 = (uint32_t)(aRow & 7);
    const uint32_t qAOff = (uint32_t)(aRow * 512);
    const uint32_t pAOff = (uint32_t)(aRow * 256);
    uint32_t kOff[4], kR7[4];
#pragma unroll
    for (int np = 0; np < 4; np++) {
        int row = np * 16 + lr + ((lm >> 1) << 3);
        kOff[np] = (uint32_t)(row * 512); kR7[np] = (uint32_t)(row & 7);
    }
    uint32_t vOff[8], vR7[8];
#pragma unroll
    for (int np = 0; np < 8; np++) {
        int row = np * 16 + lr + ((lm >> 1) << 3);
        vOff[np] = (uint32_t)(row * 256); vR7[np] = (uint32_t)(row & 7);
    }

    // prologue group: Q tile
#pragma unroll
    for (int u = 0; u < 16; u++) {
        int idx = tid + 256 * u;
        int r = idx >> 5, c4 = idx & 31;
        uint32_t doff = (uint32_t)((r * 32 + (c4 ^ (r & 7))) * 16);
        asm volatile("cp.async.cg.shared.global [%0], [%1], 16;"
            :: "r"(sQ + doff), "l"(Qg + (size_t)r * 128 + c4 * 4) : "memory");
    }
    asm volatile("cp.async.commit_group;" ::: "memory");

// K tile: 64 rows(s) x 128 cols(d), 512B rows
#define K_ISSUE(sbuf, kb) do { \
    _Pragma("unroll") \
    for (int u = 0; u < 8; u++) { \
        int idx = tid + 256 * u; \
        int r = idx >> 5, c4 = idx & 31; \
        uint32_t doff = (uint32_t)((r * 32 + (c4 ^ (r & 7))) * 16); \
        asm volatile("cp.async.cg.shared.global [%0], [%1], 16;" \
            :: "r"((sbuf) + doff), "l"(Kg + (size_t)((kb) + r) * 128 + c4 * 4) : "memory"); \
    } \
    asm volatile("cp.async.commit_group;" ::: "memory"); \
} while (0)

// Vt tile: 128 rows(d) x 64 cols(s), 256B rows
#define VT_ISSUE(sbuf, kb) do { \
    _Pragma("unroll") \
    for (int u = 0; u < 8; u++) { \
        int idx = tid + 256 * u; \
        int r = idx >> 4, c4 = idx & 15; \
        uint32_t doff = (uint32_t)((r * 16 + (c4 ^ (r & 7))) * 16); \
        asm volatile("cp.async.cg.shared.global [%0], [%1], 16;" \
            :: "r"((sbuf) + doff), "l"(Vg + (size_t)r * S_ + (kb) + c4 * 4) : "memory"); \
    } \
    asm volatile("cp.async.commit_group;" ::: "memory"); \
} while (0)

    K_ISSUE(sK0, 0);
    // Q + K[0] must land before first QK
    asm volatile("cp.async.wait_group 0;" ::: "memory");
    __syncthreads();

    float o[16][4];
#pragma unroll
    for (int nt = 0; nt < 16; nt++)
#pragma unroll
        for (int q = 0; q < 4; q++) o[nt][q] = 0.f;
    float m0 = -1e30f, m1 = -1e30f, l0 = 0.f, l1 = 0.f;

    const float inv_norm = 0.08838834764831845f;
    const int nT = 2 * qt + 2;
    const int rowg0 = qBase + wid * 16 + g;
    const int rowg1 = rowg0 + 8;

    for (int jt = 0; jt < nT; jt++) {
        const int kB = jt * 64;
        const uint32_t sVc = (jt & 1) ? sV1 : sV0;
        const uint32_t sKc = (jt & 1) ? sK1 : sK0;

        // issue this tile's V and next tile's K up front; both overlap QK+softmax
        VT_ISSUE(sVc, kB);
        if (jt + 1 < nT) K_ISSUE((jt & 1) ? sK0 : sK1, kB + 64);

        // ---------------- scores: S = Q K^T (16x64 per warp) ----------------
        float s[8][4];
#pragma unroll
        for (int nt = 0; nt < 8; nt++)
#pragma unroll
            for (int q = 0; q < 4; q++) s[nt][q] = 0.f;

#pragma unroll
        for (int k8 = 0; k8 < 16; k8++) {
            uint32_t a[4];
            ldsm4(a, sQ + qAOff + (((2 * k8 + aC) ^ aR7) << 4));
#pragma unroll
            for (int np = 0; np < 4; np++) {
                uint32_t bf[4];
                ldsm4(bf, sKc + kOff[np] + (((2 * k8 + bC) ^ kR7[np]) << 4));
                mma_tf32(s[2 * np],     a, &bf[0]);
                mma_tf32(s[2 * np + 1], a, &bf[2]);
            }
        }

        // ---------------- scale + alibi (global, L1) + causal mask ----------
        const bool domask = (jt >= 2 * qt);
        float ml0 = -1e30f, ml1 = -1e30f;
#pragma unroll
        for (int nt = 0; nt < 8; nt++) {
            int c0 = kB + nt * 8 + 2 * t;
            float2 al2 = __ldg((const float2*)&alg[c0]);
            s[nt][0] = s[nt][0] * inv_norm + al2.x;
            s[nt][1] = s[nt][1] * inv_norm + al2.y;
            s[nt][2] = s[nt][2] * inv_norm + al2.x;
            s[nt][3] = s[nt][3] * inv_norm + al2.y;
            if (domask) {
                if (c0 > rowg0)     s[nt][0] = -1e30f;
                if (c0 + 1 > rowg0) s[nt][1] = -1e30f;
                if (c0 > rowg1)     s[nt][2] = -1e30f;
                if (c0 + 1 > rowg1) s[nt][3] = -1e30f;
            }
            ml0 = fmaxf(ml0, fmaxf(s[nt][0], s[nt][1]));
            ml1 = fmaxf(ml1, fmaxf(s[nt][2], s[nt][3]));
        }
        ml0 = fmaxf(ml0, __shfl_xor_sync(0xffffffffu, ml0, 1));
        ml0 = fmaxf(ml0, __shfl_xor_sync(0xffffffffu, ml0, 2));
        ml1 = fmaxf(ml1, __shfl_xor_sync(0xffffffffu, ml1, 1));
        ml1 = fmaxf(ml1, __shfl_xor_sync(0xffffffffu, ml1, 2));

        float mn0 = fmaxf(m0, ml0), mn1 = fmaxf(m1, ml1);
        float alpha0 = __expf(m0 - mn0), alpha1 = __expf(m1 - mn1);
        m0 = mn0; m1 = mn1;

        float ls0 = 0.f, ls1 = 0.f;
#pragma unroll
        for (int nt = 0; nt < 8; nt++) {
            float p0 = __expf(s[nt][0] - mn0);
            float p1 = __expf(s[nt][1] - mn0);
            float p2 = __expf(s[nt][2] - mn1);
            float p3 = __expf(s[nt][3] - mn1);
            ls0 += p0 + p1;
            ls1 += p2 + p3;
            int c = nt * 8 + 2 * t;
            int r0p = wid * 16 + g;
            float* pp0 = &Ps[(r0p * 16 + (((c >> 2) ^ (r0p & 7)))) * 4 + (c & 3)];
            *(float2*)pp0 = make_float2(rna_tf32(p0), rna_tf32(p1));
            int r1p = r0p + 8;
            float* pp1 = &Ps[(r1p * 16 + (((c >> 2) ^ (r1p & 7)))) * 4 + (c & 3)];
            *(float2*)pp1 = make_float2(rna_tf32(p2), rna_tf32(p3));
        }
        ls0 += __shfl_xor_sync(0xffffffffu, ls0, 1);
        ls0 += __shfl_xor_sync(0xffffffffu, ls0, 2);
        ls1 += __shfl_xor_sync(0xffffffffu, ls1, 1);
        ls1 += __shfl_xor_sync(0xffffffffu, ls1, 2);
        l0 = l0 * alpha0 + ls0;
        l1 = l1 * alpha1 + ls1;

#pragma unroll
        for (int nt = 0; nt < 16; nt++) {
            o[nt][0] *= alpha0; o[nt][1] *= alpha0;
            o[nt][2] *= alpha1; o[nt][3] *= alpha1;
        }

        // single wait + single barrier per iteration:
        // V[jt] (+K[jt+1]) complete; orders all cp.asyncs vs all warps' reads,
        // and PV(jt-1) reads vs this iteration's buffer overwrites (next iter).
        asm volatile("cp.async.wait_group 0;" ::: "memory");
        __syncthreads();

        // ---------------- O += P V  (16x128 per warp, k=64) ----------------
#pragma unroll
        for (int k8 = 0; k8 < 8; k8++) {
            uint32_t a[4];
            ldsm4(a, sP + pAOff + (((2 * k8 + aC) ^ aR7) << 4));
#pragma unroll
            for (int np = 0; np < 8; np++) {
                uint32_t bf[4];
                ldsm4(bf, sVc + vOff[np] + (((2 * k8 + bC) ^ vR7[np]) << 4));
                mma_tf32(o[2 * np],     a, &bf[0]);
                mma_tf32(o[2 * np + 1], a, &bf[2]);
            }
        }
        // no trailing barrier: Vbuf[jt&1] is next overwritten in iter jt+2,
        // and the single barrier of iter jt+1 sits in between (all warps).
        // Ps is warp-local (written and read by the same warp only).
    }

    // ---------------- normalize + write ctx (tf32-rounded) ----------------
    const float inv0 = 1.f / l0, inv1 = 1.f / l1;
#pragma unroll
    for (int nt = 0; nt < 16; nt++) {
        int d = nh * HD_ + nt * 8 + 2 * t;
        float2 ov0 = { rna_tf32(o[nt][0] * inv0), rna_tf32(o[nt][1] * inv0) };
        float2 ov1 = { rna_tf32(o[nt][2] * inv1), rna_tf32(o[nt][3] * inv1) };
        *(float2*)&g_ctx[((size_t)(b * S_ + rowg0)) * H_ + d] = ov0;
        *(float2*)&g_ctx[((size_t)(b * S_ + rowg1)) * H_ + d] = ov1;
    }
}

extern "C" void kernel_launch(void* const* d_in, const int* in_sizes, int n_in,
                              void* d_out, int out_size)
{
    (void)in_sizes; (void)n_in; (void)out_size;
    const float* hidden   = (const float*)d_in[0];
    const float* residual = (const float*)d_in[1];
    const float* alibi    = (const float*)d_in[2];
    // d_in[3] = attention_mask: deterministic causal triu(k=1), applied analytically
    const float* W_qkv   = (const float*)d_in[4];
    const float* b_qkv   = (const float*)d_in[5];
    const float* W_dense = (const float*)d_in[6];
    const float* b_dense = (const float*)d_in[7];
    float* out = (float*)d_out;

    cudaFuncSetAttribute(gemm_mma_kernel, cudaFuncAttributeMaxDynamicSharedMemorySize, GSMEM);
    cudaFuncSetAttribute(attn_mma_kernel, cudaFuncAttributeMaxDynamicSharedMemorySize, AT_SMEM);

    // 0) round GEMM inputs to tf32 (RNA, unbiased)
    cvt_tf32_kernel<<<(MTOK * H_ / 4 + 255) / 256, 256>>>(hidden, 0, MTOK * H_ / 4);
    cvt_tf32_kernel<<<(NQKV * H_ / 4 + 255) / 256, 256>>>(W_qkv, 1, NQKV * H_ / 4);
    cvt_tf32_kernel<<<(H_ * H_ / 4 + 255) / 256, 256>>>(W_dense, 2, H_ * H_ / 4);

    // 1) QKV projection + bias + de-interleave scatter (V pre-transposed)
    gemm_mma_kernel<<<dim3(MTOK / 128, NQKV / 128), 256, GSMEM>>>(b_qkv, nullptr, nullptr, 0);

    // 2) causal attention with alibi — tf32 mma + ldmatrix flash kernel
    attn_mma_kernel<<<dim3(B_ * NH_, S_ / 128), 256, AT_SMEM>>>(alibi);

    // 3) dense projection + bias + residual
    gemm_mma_kernel<<<dim3(MTOK / 128, H_ / 128), 256, GSMEM>>>(b_dense, residual, out, 1);
}